// round 5
// baseline (speedup 1.0000x reference)
#include <cuda_runtime.h>
#include <math.h>

#define H    16
#define S    2048
#define D    64
#define DIMM 1024
#define SCMP 128
#define GDIM 48

#define BM 128
#define BN 128
#define BK 16

// ---------------- scratch ----------------
__device__ float d_q[H*S*D];
__device__ float d_k[H*S*D];
__device__ float d_v[H*S*D];
__device__ float d_g1[S*512];
__device__ float d_gate[S*GDIM];
__device__ float d_kc[H*SCMP*D];
__device__ float d_vc[H*SCMP*D];
__device__ float d_o1[S*DIMM];
__device__ float d_o2[S*DIMM];
__device__ float d_o3[S*DIMM];
__device__ unsigned d_bm[H*S];

enum { EPI_NONE=0, EPI_SILU=1, EPI_SIGMOID=2, EPI_HEAD=3 };

// ---------------- double-buffered fp32 GEMM ----------------
__global__ __launch_bounds__(256,2)
void gemm_big(const float* __restrict__ A,
              const float* __restrict__ Ab,
              const float* __restrict__ Ac,
              const float* __restrict__ B0,
              const float* __restrict__ B1,
              const float* __restrict__ B2,
              float* __restrict__ C0,
              float* __restrict__ C1,
              float* __restrict__ C2,
              int M, int N, int K, int epi)
{
    __shared__ __align__(16) float As[2][BK][BM];
    __shared__ __align__(16) float Bs[2][BK][BN];
    const int tid = threadIdx.x;
    const int tx = tid & 15, ty = tid >> 4;
    const int m0 = blockIdx.y * BM, n0 = blockIdx.x * BN;
    const float* B = blockIdx.z==0 ? B0 : (blockIdx.z==1 ? B1 : B2);
    float* C = blockIdx.z==0 ? C0 : (blockIdx.z==1 ? C1 : C2);

    const int arow = tid & 127;
    const int akq  = tid >> 7;
    const int bkk  = tid >> 5;
    const int bn   = (tid & 31) * 4;

    const long abase = (long)(m0 + arow) * K;
    const bool bok = (n0 + bn) < N;

    float4 ra[2], rb[2];
    float acc[8][8];
    #pragma unroll
    for (int i=0;i<8;i++)
        #pragma unroll
        for (int j=0;j<8;j++) acc[i][j]=0.f;

    const int nT = K / BK;

    #pragma unroll
    for (int i=0;i<2;i++){
        long off = abase + (akq + i*2)*4;
        float4 v = *(const float4*)(A + off);
        if (Ab){
            float4 w = *(const float4*)(Ab + off);
            float4 u = *(const float4*)(Ac + off);
            v.x+=w.x+u.x; v.y+=w.y+u.y; v.z+=w.z+u.z; v.w+=w.w+u.w;
        }
        ra[i]=v;
        rb[i]= bok ? *(const float4*)(B + (long)(bkk + i*8)*N + n0 + bn)
                   : make_float4(0.f,0.f,0.f,0.f);
    }
    #pragma unroll
    for (int i=0;i<2;i++){
        int kq=(akq+i*2)*4;
        As[0][kq+0][arow]=ra[i].x; As[0][kq+1][arow]=ra[i].y;
        As[0][kq+2][arow]=ra[i].z; As[0][kq+3][arow]=ra[i].w;
        *(float4*)&Bs[0][bkk+i*8][bn] = rb[i];
    }
    __syncthreads();

    int buf=0;
    for (int t=0;t<nT;t++){
        if (t+1<nT){
            int k0=(t+1)*BK;
            #pragma unroll
            for (int i=0;i<2;i++){
                long off = abase + k0 + (akq + i*2)*4;
                float4 v = *(const float4*)(A + off);
                if (Ab){
                    float4 w = *(const float4*)(Ab + off);
                    float4 u = *(const float4*)(Ac + off);
                    v.x+=w.x+u.x; v.y+=w.y+u.y; v.z+=w.z+u.z; v.w+=w.w+u.w;
                }
                ra[i]=v;
                rb[i]= bok ? *(const float4*)(B + (long)(k0 + bkk + i*8)*N + n0 + bn)
                           : make_float4(0.f,0.f,0.f,0.f);
            }
        }
        #pragma unroll
        for (int kk=0;kk<BK;kk++){
            float4 a0=*(const float4*)&As[buf][kk][ty*8];
            float4 a1=*(const float4*)&As[buf][kk][ty*8+4];
            float4 b0=*(const float4*)&Bs[buf][kk][tx*8];
            float4 b1=*(const float4*)&Bs[buf][kk][tx*8+4];
            float av[8]={a0.x,a0.y,a0.z,a0.w,a1.x,a1.y,a1.z,a1.w};
            float bv[8]={b0.x,b0.y,b0.z,b0.w,b1.x,b1.y,b1.z,b1.w};
            #pragma unroll
            for (int i=0;i<8;i++)
                #pragma unroll
                for (int j=0;j<8;j++) acc[i][j] += av[i]*bv[j];
        }
        if (t+1<nT){
            int nb=buf^1;
            #pragma unroll
            for (int i=0;i<2;i++){
                int kq=(akq+i*2)*4;
                As[nb][kq+0][arow]=ra[i].x; As[nb][kq+1][arow]=ra[i].y;
                As[nb][kq+2][arow]=ra[i].z; As[nb][kq+3][arow]=ra[i].w;
                *(float4*)&Bs[nb][bkk+i*8][bn] = rb[i];
            }
        }
        __syncthreads();
        buf^=1;
    }

    #pragma unroll
    for (int i=0;i<8;i++){
        int gm = m0 + ty*8 + i;
        #pragma unroll
        for (int j=0;j<8;j++){
            int gn = n0 + tx*8 + j;
            if (gn >= N) continue;
            float vv = acc[i][j];
            if (epi==EPI_SILU)         vv = vv/(1.f+__expf(-vv));
            else if (epi==EPI_SIGMOID) vv = 1.f/(1.f+__expf(-vv));
            if (epi==EPI_HEAD) C[((gn>>6)*S + gm)*D + (gn&63)] = vv;
            else               C[(long)gm*N + gn] = vv;
        }
    }
}

// ---------------- compression Phi (rewritten) ----------------
// One level: b[p][d] = silu(sum_j a[p][j] * W[j][d]), a rows contiguous [P][128].
template<int P>
__device__ __forceinline__ void phi_level(const float* __restrict__ a,
                                          float* __restrict__ b,
                                          const float* __restrict__ W, int d)
{
    float accs[P];
    #pragma unroll
    for (int p=0;p<P;p++) accs[p]=0.f;
    #pragma unroll 4
    for (int j=0;j<128;j+=4){
        float w0=W[(j+0)*64+d], w1=W[(j+1)*64+d];
        float w2=W[(j+2)*64+d], w3=W[(j+3)*64+d];
        #pragma unroll
        for (int p=0;p<P;p++){
            float4 c = *(const float4*)&a[p*128+j];
            accs[p] += c.x*w0;
            accs[p] += c.y*w1;
            accs[p] += c.z*w2;
            accs[p] += c.w*w3;
        }
    }
    #pragma unroll
    for (int p=0;p<P;p++){
        float xx = accs[p];
        b[p*64+d] = xx / (1.f + __expf(-xx));
    }
}

// grid (32, H, 2): 4 windows per 256-thread block; z=0 -> K, z=1 -> V.
__global__ __launch_bounds__(256)
void compress2(const float* __restrict__ ksrc, const float* __restrict__ vsrc,
               const float* __restrict__ pe_k, const float* __restrict__ down_k,
               const float* __restrict__ stop_k,
               const float* __restrict__ pe_v, const float* __restrict__ down_v,
               const float* __restrict__ stop_v,
               float* __restrict__ kc, float* __restrict__ vc)
{
    __shared__ __align__(16) float bufX[4*2048];
    __shared__ __align__(16) float bufY[4*1024];
    const int tid = threadIdx.x;
    const int d   = tid & 63;
    const int sub = tid >> 6;
    const int w   = blockIdx.x*4 + sub;     // 0..127
    const int h   = blockIdx.y;
    const int z   = blockIdx.z;
    const float* src  = z ? vsrc  : ksrc;
    const float* pe   = z ? pe_v  : pe_k;
    const float* down = z ? down_v: down_k;
    const float* stop = z ? stop_v: stop_k;
    float* dst        = z ? vc    : kc;

    float* X = bufX + sub*2048;
    float* Y = bufY + sub*1024;

    if (w > 0){
        int s0 = (w-1)*16;
        #pragma unroll
        for (int i=0;i<32;i++)
            X[i*64+d] = src[(h*S + s0+i)*D + d] + pe[i*64+d];
    }
    __syncthreads();

    phi_level<16>(X, Y, down,         d);  __syncthreads();
    phi_level<8> (Y, X, down + 8192,  d);  __syncthreads();
    phi_level<4> (X, Y, down + 16384, d);  __syncthreads();
    phi_level<2> (Y, X, down + 24576, d);  __syncthreads();
    phi_level<1> (X, Y, down + 32768, d);  __syncthreads();

    float a = 0.f;
    #pragma unroll
    for (int j=0;j<64;j+=4){
        float4 c = *(const float4*)&Y[j];
        a += c.x*stop[(j+0)*64+d];
        a += c.y*stop[(j+1)*64+d];
        a += c.z*stop[(j+2)*64+d];
        a += c.w*stop[(j+3)*64+d];
    }
    dst[(h*SCMP + w)*D + d] = (w > 0) ? a : 0.f;
}

// ---------------- compressed branch + conv + top-k selection ----------------
__global__ void cmp_attn(float scale)
{
    extern __shared__ float csm[];
    float* kc_s = csm;             // 8192
    float* vc_s = kc_s + 8192;     // 8192
    float* q_s  = vc_s + 8192;     // 64
    float* p_sm = q_s + 64;        // 128
    float* ps   = p_sm + 128;      // 32
    float* ps2  = ps + 32;         // 64
    float* red  = ps2 + 64;        // 4

    int h = blockIdx.y;
    int tid = threadIdx.x;
    int lane = tid & 31, wid = tid >> 5;

    for (int i=tid;i<8192;i+=128){ kc_s[i]=d_kc[h*8192+i]; vc_s[i]=d_vc[h*8192+i]; }

    for (int qi=0;qi<8;qi++){
        int q = blockIdx.x*8 + qi;
        __syncthreads();
        if (tid < 64) q_s[tid] = d_q[(h*S + q)*D + tid];
        __syncthreads();

        int r = q >> 4;
        float sc = -INFINITY;
        {
            bool ok = (tid <= r-1) || (tid==0 && r<32);
            if (ok){
                float a=0.f;
                #pragma unroll
                for (int dd=0;dd<64;dd++) a += q_s[dd]*kc_s[tid*64+dd];
                sc = a*scale;
            }
        }
        float v = sc;
        #pragma unroll
        for (int off=16;off;off>>=1) v = fmaxf(v, __shfl_xor_sync(0xffffffffu,v,off));
        if (lane==0) red[wid]=v;
        __syncthreads();
        float m = fmaxf(fmaxf(red[0],red[1]),fmaxf(red[2],red[3]));
        float p = __expf(sc - m);
        p_sm[tid] = p;
        __syncthreads();
        float sv = p;
        #pragma unroll
        for (int off=16;off;off>>=1) sv += __shfl_xor_sync(0xffffffffu,sv,off);
        if (lane==0) red[wid]=sv;
        __syncthreads();
        float l = red[0]+red[1]+red[2]+red[3];

        if (wid == 3){
            int n = lane;
            float a = 2.f*(p_sm[4*n] + p_sm[4*n+1] + p_sm[4*n+2]) + p_sm[4*n+3];
            if (4*n-1 >= 0) a += p_sm[4*n-1];
            ps[n] = a;
            __syncwarp();
            float mv = ps[n];
            int cnt = 0;
            #pragma unroll
            for (int i2=0;i2<32;i2++){
                float vi = ps[i2];
                cnt += (vi > mv) || (vi == mv && i2 < n);
            }
            bool sel = (cnt < 16) && (n < (q >> 6));
            unsigned msk = __ballot_sync(0xffffffffu, sel);
            if (lane==0) d_bm[h*S + q] = msk;
        }
        float a;
        if (tid < 64){
            a = 0.f;
            for (int j=0;j<64;j++) a += p_sm[j]*vc_s[j*64+tid];
        } else {
            float b = 0.f;
            int dd = tid - 64;
            for (int j=64;j<128;j++) b += p_sm[j]*vc_s[j*64+dd];
            ps2[dd] = b;
            a = 0.f;
        }
        __syncthreads();
        if (tid < 64){
            float g0 = d_gate[q*GDIM + h*3 + 0];
            d_o1[q*DIMM + h*64 + tid] = g0 * ((a + ps2[tid]) / l);
        }
    }
}

// ---------------- flash-style sparse attention ----------------
template<int MODE>
__global__ void attn_flash(float scale)
{
    extern __shared__ float fsm[];
    float* q_s  = fsm;
    float* kv_s = q_s  + 64*65;
    float* p_s  = kv_s + 64*65;
    float* m_s  = p_s  + 64*65;
    float* l_s  = m_s + 64;
    unsigned* msk_s = (unsigned*)(l_s + 64);
    unsigned* u_s   = msk_s + 64;

    int tq = blockIdx.x, h = blockIdx.y;
    int q0 = tq*64;
    int tid = threadIdx.x;
    int tx = tid & 15, ty = tid >> 4;

    #pragma unroll
    for (int r2=0;r2<16;r2++){
        int li = tid + r2*256;
        int row = li>>6, col = li&63;
        q_s[row*65+col] = d_q[(h*S + q0+row)*D + col];
    }
    if (tid < 64){
        m_s[tid] = -INFINITY; l_s[tid] = 0.f;
        if (MODE==0) msk_s[tid] = d_bm[h*S + q0 + tid];
    }
    __syncthreads();

    unsigned uni = 0xFFFFFFFFu;
    if (MODE==0){
        if (tid==0){
            unsigned u=0;
            for (int i=0;i<64;i++) u |= msk_s[i];
            u_s[0]=u;
        }
        __syncthreads();
        uni = u_s[0];
    }

    int nlo, nhi;
    if (MODE==0){ nlo=0; nhi=(uni==0u)?0:tq; }
    else { nlo = tq-8; if (nlo<0) nlo=0; nhi = tq+1; }

    float acc[4][4];
    #pragma unroll
    for (int i=0;i<4;i++)
        #pragma unroll
        for (int j=0;j<4;j++) acc[i][j]=0.f;

    for (int n=nlo;n<nhi;n++){
        if (MODE==0 && !((uni>>n)&1u)) continue;

        #pragma unroll
        for (int r2=0;r2<16;r2++){
            int li = tid + r2*256;
            int row = li>>6, col = li&63;
            kv_s[row*65+col] = d_k[(h*S + n*64+row)*D + col];
        }
        __syncthreads();

        float s[4][4];
        #pragma unroll
        for (int i=0;i<4;i++)
            #pragma unroll
            for (int j=0;j<4;j++) s[i][j]=0.f;
        #pragma unroll 8
        for (int dd=0;dd<64;dd++){
            float qv[4], kv[4];
            #pragma unroll
            for (int i=0;i<4;i++) qv[i]=q_s[(ty*4+i)*65 + dd];
            #pragma unroll
            for (int j=0;j<4;j++) kv[j]=kv_s[(tx*4+j)*65 + dd];
            #pragma unroll
            for (int i=0;i<4;i++)
                #pragma unroll
                for (int j=0;j<4;j++) s[i][j] += qv[i]*kv[j];
        }

        float amn[4], anl[4];
        #pragma unroll
        for (int i=0;i<4;i++){
            int qi = ty*4+i;
            int qg = q0 + qi;
            unsigned mbits = (MODE==0) ? msk_s[qi] : 0u;
            float rm = -INFINITY;
            #pragma unroll
            for (int j=0;j<4;j++){
                bool ok;
                if (MODE==0) ok = (mbits>>n)&1u;
                else { int t = n*64 + tx*4 + j; ok = (t <= qg) && (qg - t <= 512); }
                float val = ok ? s[i][j]*scale : -INFINITY;
                s[i][j]=val;
                rm = fmaxf(rm, val);
            }
            #pragma unroll
            for (int off=8;off;off>>=1) rm = fmaxf(rm, __shfl_xor_sync(0xffffffffu, rm, off));
            float mo = m_s[qi];
            float mn = fmaxf(mo, rm);
            float alpha = 1.f, ts = 0.f;
            if (mn == -INFINITY){
                #pragma unroll
                for (int j=0;j<4;j++) s[i][j]=0.f;
            } else {
                alpha = __expf(mo - mn);
                #pragma unroll
                for (int j=0;j<4;j++){ float pp = __expf(s[i][j]-mn); s[i][j]=pp; ts += pp; }
            }
            #pragma unroll
            for (int off=8;off;off>>=1) ts += __shfl_xor_sync(0xffffffffu, ts, off);
            #pragma unroll
            for (int j=0;j<4;j++) p_s[qi*65 + tx*4 + j] = s[i][j];
            #pragma unroll
            for (int j=0;j<4;j++) acc[i][j] *= alpha;
            amn[i]=mn; anl[i]=l_s[qi]*alpha + ts;
        }
        __syncthreads();
        if (tx==0){
            #pragma unroll
            for (int i=0;i<4;i++){ m_s[ty*4+i]=amn[i]; l_s[ty*4+i]=anl[i]; }
        }
        #pragma unroll
        for (int r2=0;r2<16;r2++){
            int li = tid + r2*256;
            int row = li>>6, col = li&63;
            kv_s[row*65+col] = d_v[(h*S + n*64+row)*D + col];
        }
        __syncthreads();
        #pragma unroll 4
        for (int kk=0;kk<64;kk++){
            float pv[4], vv[4];
            #pragma unroll
            for (int i=0;i<4;i++) pv[i]=p_s[(ty*4+i)*65+kk];
            #pragma unroll
            for (int j=0;j<4;j++) vv[j]=kv_s[kk*65 + tx*4 + j];
            #pragma unroll
            for (int i=0;i<4;i++)
                #pragma unroll
                for (int j=0;j<4;j++) acc[i][j] += pv[i]*vv[j];
        }
        __syncthreads();
    }

    float* outp = (MODE==0) ? d_o2 : d_o3;
    #pragma unroll
    for (int i=0;i<4;i++){
        int qg = q0 + ty*4 + i;
        float l = l_s[ty*4+i];
        float inv = (l > 0.f) ? 1.f/l : 0.f;
        float g = d_gate[qg*GDIM + h*3 + (MODE==0 ? 1 : 2)];
        #pragma unroll
        for (int j=0;j<4;j++)
            outp[qg*DIMM + h*64 + tx*4 + j] = g * acc[i][j] * inv;
    }
}

// ---------------- launch ----------------
static cudaStream_t sA = nullptr, sB = nullptr;
static cudaEvent_t e0, e_qkv, e_gate, e_cmp, e_f0, e_f1;

extern "C" void kernel_launch(void* const* d_in, const int* in_sizes, int n_in,
                              void* d_out, int out_size)
{
    (void)in_sizes; (void)n_in; (void)out_size;
    const float* x      = (const float*)d_in[0];
    const float* wq     = (const float*)d_in[1];
    const float* wk     = (const float*)d_in[2];
    const float* wv     = (const float*)d_in[3];
    const float* wo     = (const float*)d_in[4];
    const float* gw1    = (const float*)d_in[5];
    const float* gw2    = (const float*)d_in[6];
    const float* pe_k   = (const float*)d_in[7];
    const float* down_k = (const float*)d_in[8];
    const float* stop_k = (const float*)d_in[9];
    const float* pe_v   = (const float*)d_in[10];
    const float* down_v = (const float*)d_in[11];
    const float* stop_v = (const float*)d_in[12];

    if (!sA){
        cudaStreamCreateWithFlags(&sA, cudaStreamNonBlocking);
        cudaStreamCreateWithFlags(&sB, cudaStreamNonBlocking);
        cudaEventCreateWithFlags(&e0,     cudaEventDisableTiming);
        cudaEventCreateWithFlags(&e_qkv,  cudaEventDisableTiming);
        cudaEventCreateWithFlags(&e_gate, cudaEventDisableTiming);
        cudaEventCreateWithFlags(&e_cmp,  cudaEventDisableTiming);
        cudaEventCreateWithFlags(&e_f0,   cudaEventDisableTiming);
        cudaEventCreateWithFlags(&e_f1,   cudaEventDisableTiming);
        const int CSM = (8192+8192+64+128+32+64+4)*4;
        cudaFuncSetAttribute(cmp_attn, cudaFuncAttributeMaxDynamicSharedMemorySize, CSM);
        const int FSM = (3*64*65 + 64 + 64)*4 + 65*4;
        cudaFuncSetAttribute(attn_flash<0>, cudaFuncAttributeMaxDynamicSharedMemorySize, FSM);
        cudaFuncSetAttribute(attn_flash<1>, cudaFuncAttributeMaxDynamicSharedMemorySize, FSM);
    }

    float *q_p, *k_p, *v_p, *g1_p, *gate_p, *kc_p, *vc_p, *o1_p, *o2_p, *o3_p;
    cudaGetSymbolAddress((void**)&q_p,    d_q);
    cudaGetSymbolAddress((void**)&k_p,    d_k);
    cudaGetSymbolAddress((void**)&v_p,    d_v);
    cudaGetSymbolAddress((void**)&g1_p,   d_g1);
    cudaGetSymbolAddress((void**)&gate_p, d_gate);
    cudaGetSymbolAddress((void**)&kc_p,   d_kc);
    cudaGetSymbolAddress((void**)&vc_p,   d_vc);
    cudaGetSymbolAddress((void**)&o1_p,   d_o1);
    cudaGetSymbolAddress((void**)&o2_p,   d_o2);
    cudaGetSymbolAddress((void**)&o3_p,   d_o3);

    const float scale = 0.125f;
    const int CSM = (8192+8192+64+128+32+64+4)*4;
    const int FSM = (3*64*65 + 64 + 64)*4 + 65*4;

    cudaEventRecord(e0, 0);
    cudaStreamWaitEvent(sA, e0, 0);

    // stream0: fused QKV projection
    gemm_big<<<dim3(8,16,3),256>>>(x, nullptr, nullptr, wq, wk, wv,
                                   q_p, k_p, v_p, S, 1024, DIMM, EPI_HEAD);
    cudaEventRecord(e_qkv, 0);

    // sA: gate chain
    gemm_big<<<dim3(4,16,1),256,0,sA>>>(x, nullptr, nullptr, gw1, gw1, gw1,
                                        g1_p, g1_p, g1_p, S, 512, DIMM, EPI_SILU);
    gemm_big<<<dim3(1,16,1),256,0,sA>>>(g1_p, nullptr, nullptr, gw2, gw2, gw2,
                                        gate_p, gate_p, gate_p, S, GDIM, 512, EPI_SIGMOID);
    cudaEventRecord(e_gate, sA);

    // stream0: fused K+V compression, then compressed branch (+ masks)
    compress2<<<dim3(32,16,2),256>>>(k_p, v_p, pe_k, down_k, stop_k,
                                     pe_v, down_v, stop_v, kc_p, vc_p);
    cudaStreamWaitEvent(0, e_gate, 0);
    cmp_attn<<<dim3(S/8,16),128,CSM>>>(scale);
    cudaEventRecord(e_cmp, 0);

    // sA: sliding-window branch
    cudaStreamWaitEvent(sA, e_qkv, 0);
    attn_flash<1><<<dim3(S/64,16),256,FSM,sA>>>(scale);
    cudaEventRecord(e_f1, sA);

    // sB: selection branch (needs masks + gate)
    cudaStreamWaitEvent(sB, e_cmp, 0);
    cudaStreamWaitEvent(sB, e_gate, 0);
    attn_flash<0><<<dim3(S/64,16),256,FSM,sB>>>(scale);
    cudaEventRecord(e_f0, sB);

    // join + output projection
    cudaStreamWaitEvent(0, e_f1, 0);
    cudaStreamWaitEvent(0, e_f0, 0);
    gemm_big<<<dim3(8,16,1),256>>>(o1_p, o2_p, o3_p, wo, wo, wo,
                                   (float*)d_out, (float*)d_out, (float*)d_out,
                                   S, DIMM, DIMM, EPI_NONE);
}

// round 6
// speedup vs baseline: 1.0410x; 1.0410x over previous
#include <cuda_runtime.h>
#include <math.h>

#define H    16
#define S    2048
#define D    64
#define DIMM 1024
#define SCMP 128
#define GDIM 48

#define BM 128
#define BN 128
#define BK 16

#define ST 68   // shared row stride (floats) for flash tiles

// ---------------- scratch ----------------
__device__ float d_q[H*S*D];
__device__ float d_k[H*S*D];
__device__ float d_v[H*S*D];
__device__ float d_g1[S*512];
__device__ float d_gate[S*GDIM];
__device__ float d_kc[H*SCMP*D];
__device__ float d_vc[H*SCMP*D];
__device__ float d_o1[S*DIMM];
__device__ float d_o2[S*DIMM];
__device__ float d_o3[S*DIMM];
__device__ unsigned d_bm[H*S];

enum { EPI_NONE=0, EPI_SILU=1, EPI_SIGMOID=2, EPI_HEAD=3 };

// ---------------- double-buffered fp32 GEMM ----------------
__global__ __launch_bounds__(256,2)
void gemm_big(const float* __restrict__ A,
              const float* __restrict__ Ab,
              const float* __restrict__ Ac,
              const float* __restrict__ B0,
              const float* __restrict__ B1,
              const float* __restrict__ B2,
              float* __restrict__ C0,
              float* __restrict__ C1,
              float* __restrict__ C2,
              int M, int N, int K, int epi)
{
    __shared__ __align__(16) float As[2][BK][BM];
    __shared__ __align__(16) float Bs[2][BK][BN];
    const int tid = threadIdx.x;
    const int tx = tid & 15, ty = tid >> 4;
    const int m0 = blockIdx.y * BM, n0 = blockIdx.x * BN;
    const float* B = blockIdx.z==0 ? B0 : (blockIdx.z==1 ? B1 : B2);
    float* C = blockIdx.z==0 ? C0 : (blockIdx.z==1 ? C1 : C2);

    const int arow = tid & 127;
    const int akq  = tid >> 7;
    const int bkk  = tid >> 5;
    const int bn   = (tid & 31) * 4;

    const long abase = (long)(m0 + arow) * K;
    const bool bok = (n0 + bn) < N;

    float4 ra[2], rb[2];
    float acc[8][8];
    #pragma unroll
    for (int i=0;i<8;i++)
        #pragma unroll
        for (int j=0;j<8;j++) acc[i][j]=0.f;

    const int nT = K / BK;

    #pragma unroll
    for (int i=0;i<2;i++){
        long off = abase + (akq + i*2)*4;
        float4 v = *(const float4*)(A + off);
        if (Ab){
            float4 w = *(const float4*)(Ab + off);
            float4 u = *(const float4*)(Ac + off);
            v.x+=w.x+u.x; v.y+=w.y+u.y; v.z+=w.z+u.z; v.w+=w.w+u.w;
        }
        ra[i]=v;
        rb[i]= bok ? *(const float4*)(B + (long)(bkk + i*8)*N + n0 + bn)
                   : make_float4(0.f,0.f,0.f,0.f);
    }
    #pragma unroll
    for (int i=0;i<2;i++){
        int kq=(akq+i*2)*4;
        As[0][kq+0][arow]=ra[i].x; As[0][kq+1][arow]=ra[i].y;
        As[0][kq+2][arow]=ra[i].z; As[0][kq+3][arow]=ra[i].w;
        *(float4*)&Bs[0][bkk+i*8][bn] = rb[i];
    }
    __syncthreads();

    int buf=0;
    for (int t=0;t<nT;t++){
        if (t+1<nT){
            int k0=(t+1)*BK;
            #pragma unroll
            for (int i=0;i<2;i++){
                long off = abase + k0 + (akq + i*2)*4;
                float4 v = *(const float4*)(A + off);
                if (Ab){
                    float4 w = *(const float4*)(Ab + off);
                    float4 u = *(const float4*)(Ac + off);
                    v.x+=w.x+u.x; v.y+=w.y+u.y; v.z+=w.z+u.z; v.w+=w.w+u.w;
                }
                ra[i]=v;
                rb[i]= bok ? *(const float4*)(B + (long)(k0 + bkk + i*8)*N + n0 + bn)
                           : make_float4(0.f,0.f,0.f,0.f);
            }
        }
        #pragma unroll
        for (int kk=0;kk<BK;kk++){
            float4 a0=*(const float4*)&As[buf][kk][ty*8];
            float4 a1=*(const float4*)&As[buf][kk][ty*8+4];
            float4 b0=*(const float4*)&Bs[buf][kk][tx*8];
            float4 b1=*(const float4*)&Bs[buf][kk][tx*8+4];
            float av[8]={a0.x,a0.y,a0.z,a0.w,a1.x,a1.y,a1.z,a1.w};
            float bv[8]={b0.x,b0.y,b0.z,b0.w,b1.x,b1.y,b1.z,b1.w};
            #pragma unroll
            for (int i=0;i<8;i++)
                #pragma unroll
                for (int j=0;j<8;j++) acc[i][j] += av[i]*bv[j];
        }
        if (t+1<nT){
            int nb=buf^1;
            #pragma unroll
            for (int i=0;i<2;i++){
                int kq=(akq+i*2)*4;
                As[nb][kq+0][arow]=ra[i].x; As[nb][kq+1][arow]=ra[i].y;
                As[nb][kq+2][arow]=ra[i].z; As[nb][kq+3][arow]=ra[i].w;
                *(float4*)&Bs[nb][bkk+i*8][bn] = rb[i];
            }
        }
        __syncthreads();
        buf^=1;
    }

    #pragma unroll
    for (int i=0;i<8;i++){
        int gm = m0 + ty*8 + i;
        #pragma unroll
        for (int j=0;j<8;j++){
            int gn = n0 + tx*8 + j;
            if (gn >= N) continue;
            float vv = acc[i][j];
            if (epi==EPI_SILU)         vv = vv/(1.f+__expf(-vv));
            else if (epi==EPI_SIGMOID) vv = 1.f/(1.f+__expf(-vv));
            if (epi==EPI_HEAD) C[((gn>>6)*S + gm)*D + (gn&63)] = vv;
            else               C[(long)gm*N + gn] = vv;
        }
    }
}

// ---------------- compression Phi ----------------
template<int P>
__device__ __forceinline__ void phi_level(const float* __restrict__ a,
                                          float* __restrict__ b,
                                          const float* __restrict__ W, int d)
{
    float accs[P];
    #pragma unroll
    for (int p=0;p<P;p++) accs[p]=0.f;
    #pragma unroll 4
    for (int j=0;j<128;j+=4){
        float w0=W[(j+0)*64+d], w1=W[(j+1)*64+d];
        float w2=W[(j+2)*64+d], w3=W[(j+3)*64+d];
        #pragma unroll
        for (int p=0;p<P;p++){
            float4 c = *(const float4*)&a[p*128+j];
            accs[p] += c.x*w0;
            accs[p] += c.y*w1;
            accs[p] += c.z*w2;
            accs[p] += c.w*w3;
        }
    }
    #pragma unroll
    for (int p=0;p<P;p++){
        float xx = accs[p];
        b[p*64+d] = xx / (1.f + __expf(-xx));
    }
}

__global__ __launch_bounds__(256)
void compress2(const float* __restrict__ ksrc, const float* __restrict__ vsrc,
               const float* __restrict__ pe_k, const float* __restrict__ down_k,
               const float* __restrict__ stop_k,
               const float* __restrict__ pe_v, const float* __restrict__ down_v,
               const float* __restrict__ stop_v,
               float* __restrict__ kc, float* __restrict__ vc)
{
    __shared__ __align__(16) float bufX[4*2048];
    __shared__ __align__(16) float bufY[4*1024];
    const int tid = threadIdx.x;
    const int d   = tid & 63;
    const int sub = tid >> 6;
    const int w   = blockIdx.x*4 + sub;
    const int h   = blockIdx.y;
    const int z   = blockIdx.z;
    const float* src  = z ? vsrc  : ksrc;
    const float* pe   = z ? pe_v  : pe_k;
    const float* down = z ? down_v: down_k;
    const float* stop = z ? stop_v: stop_k;
    float* dst        = z ? vc    : kc;

    float* X = bufX + sub*2048;
    float* Y = bufY + sub*1024;

    if (w > 0){
        int s0 = (w-1)*16;
        #pragma unroll
        for (int i=0;i<32;i++)
            X[i*64+d] = src[(h*S + s0+i)*D + d] + pe[i*64+d];
    }
    __syncthreads();

    phi_level<16>(X, Y, down,         d);  __syncthreads();
    phi_level<8> (Y, X, down + 8192,  d);  __syncthreads();
    phi_level<4> (X, Y, down + 16384, d);  __syncthreads();
    phi_level<2> (Y, X, down + 24576, d);  __syncthreads();
    phi_level<1> (X, Y, down + 32768, d);  __syncthreads();

    float a = 0.f;
    #pragma unroll
    for (int j=0;j<64;j+=4){
        float4 c = *(const float4*)&Y[j];
        a += c.x*stop[(j+0)*64+d];
        a += c.y*stop[(j+1)*64+d];
        a += c.z*stop[(j+2)*64+d];
        a += c.w*stop[(j+3)*64+d];
    }
    dst[(h*SCMP + w)*D + d] = (w > 0) ? a : 0.f;
}

// ---------------- compressed branch + conv + top-k selection ----------------
__global__ void cmp_attn(float scale)
{
    extern __shared__ float csm[];
    float* kc_s = csm;
    float* vc_s = kc_s + 8192;
    float* q_s  = vc_s + 8192;
    float* p_sm = q_s + 64;
    float* ps   = p_sm + 128;
    float* ps2  = ps + 32;
    float* red  = ps2 + 64;

    int h = blockIdx.y;
    int tid = threadIdx.x;
    int lane = tid & 31, wid = tid >> 5;

    for (int i=tid;i<8192;i+=128){ kc_s[i]=d_kc[h*8192+i]; vc_s[i]=d_vc[h*8192+i]; }

    for (int qi=0;qi<8;qi++){
        int q = blockIdx.x*8 + qi;
        __syncthreads();
        if (tid < 64) q_s[tid] = d_q[(h*S + q)*D + tid];
        __syncthreads();

        int r = q >> 4;
        float sc = -INFINITY;
        {
            bool ok = (tid <= r-1) || (tid==0 && r<32);
            if (ok){
                float a=0.f;
                #pragma unroll
                for (int dd=0;dd<64;dd++) a += q_s[dd]*kc_s[tid*64+dd];
                sc = a*scale;
            }
        }
        float v = sc;
        #pragma unroll
        for (int off=16;off;off>>=1) v = fmaxf(v, __shfl_xor_sync(0xffffffffu,v,off));
        if (lane==0) red[wid]=v;
        __syncthreads();
        float m = fmaxf(fmaxf(red[0],red[1]),fmaxf(red[2],red[3]));
        float p = __expf(sc - m);
        p_sm[tid] = p;
        __syncthreads();
        float sv = p;
        #pragma unroll
        for (int off=16;off;off>>=1) sv += __shfl_xor_sync(0xffffffffu,sv,off);
        if (lane==0) red[wid]=sv;
        __syncthreads();
        float l = red[0]+red[1]+red[2]+red[3];

        if (wid == 3){
            int n = lane;
            float a = 2.f*(p_sm[4*n] + p_sm[4*n+1] + p_sm[4*n+2]) + p_sm[4*n+3];
            if (4*n-1 >= 0) a += p_sm[4*n-1];
            ps[n] = a;
            __syncwarp();
            float mv = ps[n];
            int cnt = 0;
            #pragma unroll
            for (int i2=0;i2<32;i2++){
                float vi = ps[i2];
                cnt += (vi > mv) || (vi == mv && i2 < n);
            }
            bool sel = (cnt < 16) && (n < (q >> 6));
            unsigned msk = __ballot_sync(0xffffffffu, sel);
            if (lane==0) d_bm[h*S + q] = msk;
        }
        float a;
        if (tid < 64){
            a = 0.f;
            for (int j=0;j<64;j++) a += p_sm[j]*vc_s[j*64+tid];
        } else {
            float b = 0.f;
            int dd = tid - 64;
            for (int j=64;j<128;j++) b += p_sm[j]*vc_s[j*64+dd];
            ps2[dd] = b;
            a = 0.f;
        }
        __syncthreads();
        if (tid < 64){
            float g0 = d_gate[q*GDIM + h*3 + 0];
            d_o1[q*DIMM + h*64 + tid] = g0 * ((a + ps2[tid]) / l);
        }
    }
}

// ---------------- flash-style sparse attention (float4-vectorized) ----------------
// MODE 0 = selection (d_o2), MODE 1 = sliding window (d_o3)
// smem: q_s[64][ST], kT_s[64][ST] (transposed K: [d][key]), v_s[64][ST], p_s[64][ST]
template<int MODE>
__global__ __launch_bounds__(256) void attn_flash(float scale)
{
    extern __shared__ float fsm[];
    float* q_s  = fsm;              // 64*ST
    float* kT_s = q_s  + 64*ST;     // 64*ST
    float* v_s  = kT_s + 64*ST;     // 64*ST
    float* p_s  = v_s  + 64*ST;     // 64*ST
    float* m_s  = p_s  + 64*ST;     // 64
    float* l_s  = m_s + 64;         // 64
    unsigned* msk_s = (unsigned*)(l_s + 64);  // 64
    unsigned* u_s   = msk_s + 64;             // 1

    int tq = blockIdx.x, h = blockIdx.y;
    int q0 = tq*64;
    int tid = threadIdx.x;
    int tx = tid & 15, ty = tid >> 4;

    // load Q (float4)
    #pragma unroll
    for (int r2=0;r2<4;r2++){
        int li = tid + r2*256;
        int row = li >> 4, c4 = (li & 15)*4;
        *(float4*)&q_s[row*ST + c4] = *(const float4*)&d_q[(h*S + q0+row)*D + c4];
    }
    if (tid < 64){
        m_s[tid] = -INFINITY; l_s[tid] = 0.f;
        if (MODE==0) msk_s[tid] = d_bm[h*S + q0 + tid];
    }
    __syncthreads();

    unsigned uni = 0xFFFFFFFFu;
    if (MODE==0){
        if (tid==0){
            unsigned u=0;
            for (int i=0;i<64;i++) u |= msk_s[i];
            u_s[0]=u;
        }
        __syncthreads();
        uni = u_s[0];
    }

    int nlo, nhi;
    if (MODE==0){ nlo=0; nhi=(uni==0u)?0:tq; }
    else { nlo = tq-8; if (nlo<0) nlo=0; nhi = tq+1; }

    float acc[4][4];
    #pragma unroll
    for (int i=0;i<4;i++)
        #pragma unroll
        for (int j=0;j<4;j++) acc[i][j]=0.f;

    for (int n=nlo;n<nhi;n++){
        if (MODE==0 && !((uni>>n)&1u)) continue;

        // load K transposed + V natural
        #pragma unroll
        for (int r2=0;r2<4;r2++){
            int li = tid + r2*256;
            int row = li >> 4, c4 = (li & 15)*4;
            float4 kv = *(const float4*)&d_k[(h*S + n*64+row)*D + c4];
            kT_s[(c4+0)*ST + row] = kv.x;
            kT_s[(c4+1)*ST + row] = kv.y;
            kT_s[(c4+2)*ST + row] = kv.z;
            kT_s[(c4+3)*ST + row] = kv.w;
            *(float4*)&v_s[row*ST + c4] = *(const float4*)&d_v[(h*S + n*64+row)*D + c4];
        }
        __syncthreads();

        // S = Q K^T (64x64), 4x4 per thread, float4 over d
        float s[4][4];
        #pragma unroll
        for (int i=0;i<4;i++)
            #pragma unroll
            for (int j=0;j<4;j++) s[i][j]=0.f;
        #pragma unroll
        for (int dd=0;dd<64;dd+=4){
            float4 qv[4], kv[4];
            #pragma unroll
            for (int i=0;i<4;i++) qv[i] = *(const float4*)&q_s[(ty*4+i)*ST + dd];
            #pragma unroll
            for (int c=0;c<4;c++) kv[c] = *(const float4*)&kT_s[(dd+c)*ST + tx*4];
            #pragma unroll
            for (int i=0;i<4;i++){
                s[i][0] += qv[i].x*kv[0].x + qv[i].y*kv[1].x + qv[i].z*kv[2].x + qv[i].w*kv[3].x;
                s[i][1] += qv[i].x*kv[0].y + qv[i].y*kv[1].y + qv[i].z*kv[2].y + qv[i].w*kv[3].y;
                s[i][2] += qv[i].x*kv[0].z + qv[i].y*kv[1].z + qv[i].z*kv[2].z + qv[i].w*kv[3].z;
                s[i][3] += qv[i].x*kv[0].w + qv[i].y*kv[1].w + qv[i].z*kv[2].w + qv[i].w*kv[3].w;
            }
        }

        // masked streaming softmax
        float amn[4], anl[4];
        #pragma unroll
        for (int i=0;i<4;i++){
            int qi = ty*4+i;
            int qg = q0 + qi;
            unsigned mbits = (MODE==0) ? msk_s[qi] : 0u;
            float rm = -INFINITY;
            #pragma unroll
            for (int j=0;j<4;j++){
                bool ok;
                if (MODE==0) ok = (mbits>>n)&1u;
                else { int t = n*64 + tx*4 + j; ok = (t <= qg) && (qg - t <= 512); }
                float val = ok ? s[i][j]*scale : -INFINITY;
                s[i][j]=val;
                rm = fmaxf(rm, val);
            }
            #pragma unroll
            for (int off=8;off;off>>=1) rm = fmaxf(rm, __shfl_xor_sync(0xffffffffu, rm, off));
            float mo = m_s[qi];
            float mn = fmaxf(mo, rm);
            float alpha = 1.f, ts = 0.f;
            if (mn == -INFINITY){
                #pragma unroll
                for (int j=0;j<4;j++) s[i][j]=0.f;
            } else {
                alpha = __expf(mo - mn);
                #pragma unroll
                for (int j=0;j<4;j++){ float pp = __expf(s[i][j]-mn); s[i][j]=pp; ts += pp; }
            }
            #pragma unroll
            for (int off=8;off;off>>=1) ts += __shfl_xor_sync(0xffffffffu, ts, off);
            *(float4*)&p_s[qi*ST + tx*4] = make_float4(s[i][0],s[i][1],s[i][2],s[i][3]);
            #pragma unroll
            for (int j=0;j<4;j++) acc[i][j] *= alpha;
            amn[i]=mn; anl[i]=l_s[qi]*alpha + ts;
        }
        __syncthreads();
        if (tx==0){
            #pragma unroll
            for (int i=0;i<4;i++){ m_s[ty*4+i]=amn[i]; l_s[ty*4+i]=anl[i]; }
        }

        // O += P V, float4 over keys
        #pragma unroll
        for (int kk=0;kk<64;kk+=4){
            float4 pv[4], vv[4];
            #pragma unroll
            for (int i=0;i<4;i++) pv[i] = *(const float4*)&p_s[(ty*4+i)*ST + kk];
            #pragma unroll
            for (int c=0;c<4;c++) vv[c] = *(const float4*)&v_s[(kk+c)*ST + tx*4];
            #pragma unroll
            for (int i=0;i<4;i++){
                acc[i][0] += pv[i].x*vv[0].x + pv[i].y*vv[1].x + pv[i].z*vv[2].x + pv[i].w*vv[3].x;
                acc[i][1] += pv[i].x*vv[0].y + pv[i].y*vv[1].y + pv[i].z*vv[2].y + pv[i].w*vv[3].y;
                acc[i][2] += pv[i].x*vv[0].z + pv[i].y*vv[1].z + pv[i].z*vv[2].z + pv[i].w*vv[3].z;
                acc[i][3] += pv[i].x*vv[0].w + pv[i].y*vv[1].w + pv[i].z*vv[2].w + pv[i].w*vv[3].w;
            }
        }
        __syncthreads();
    }

    float* outp = (MODE==0) ? d_o2 : d_o3;
    #pragma unroll
    for (int i=0;i<4;i++){
        int qg = q0 + ty*4 + i;
        float l = l_s[ty*4+i];
        float inv = (l > 0.f) ? 1.f/l : 0.f;
        float g = d_gate[qg*GDIM + h*3 + (MODE==0 ? 1 : 2)];
        #pragma unroll
        for (int j=0;j<4;j++)
            outp[qg*DIMM + h*64 + tx*4 + j] = g * acc[i][j] * inv;
    }
}

// ---------------- launch ----------------
static cudaStream_t sA = nullptr, sB = nullptr;
static cudaEvent_t e0, e_qkv, e_gate, e_cmp, e_f0, e_f1;

extern "C" void kernel_launch(void* const* d_in, const int* in_sizes, int n_in,
                              void* d_out, int out_size)
{
    (void)in_sizes; (void)n_in; (void)out_size;
    const float* x      = (const float*)d_in[0];
    const float* wq     = (const float*)d_in[1];
    const float* wk     = (const float*)d_in[2];
    const float* wv     = (const float*)d_in[3];
    const float* wo     = (const float*)d_in[4];
    const float* gw1    = (const float*)d_in[5];
    const float* gw2    = (const float*)d_in[6];
    const float* pe_k   = (const float*)d_in[7];
    const float* down_k = (const float*)d_in[8];
    const float* stop_k = (const float*)d_in[9];
    const float* pe_v   = (const float*)d_in[10];
    const float* down_v = (const float*)d_in[11];
    const float* stop_v = (const float*)d_in[12];

    const int CSM = (8192+8192+64+128+32+64+4)*4;
    const int FSM = (4*64*ST + 64 + 64)*4 + 64*4 + 16;

    if (!sA){
        cudaStreamCreateWithFlags(&sA, cudaStreamNonBlocking);
        cudaStreamCreateWithFlags(&sB, cudaStreamNonBlocking);
        cudaEventCreateWithFlags(&e0,     cudaEventDisableTiming);
        cudaEventCreateWithFlags(&e_qkv,  cudaEventDisableTiming);
        cudaEventCreateWithFlags(&e_gate, cudaEventDisableTiming);
        cudaEventCreateWithFlags(&e_cmp,  cudaEventDisableTiming);
        cudaEventCreateWithFlags(&e_f0,   cudaEventDisableTiming);
        cudaEventCreateWithFlags(&e_f1,   cudaEventDisableTiming);
        cudaFuncSetAttribute(cmp_attn, cudaFuncAttributeMaxDynamicSharedMemorySize, CSM);
        cudaFuncSetAttribute(attn_flash<0>, cudaFuncAttributeMaxDynamicSharedMemorySize, FSM);
        cudaFuncSetAttribute(attn_flash<1>, cudaFuncAttributeMaxDynamicSharedMemorySize, FSM);
    }

    float *q_p, *k_p, *v_p, *g1_p, *gate_p, *kc_p, *vc_p, *o1_p, *o2_p, *o3_p;
    cudaGetSymbolAddress((void**)&q_p,    d_q);
    cudaGetSymbolAddress((void**)&k_p,    d_k);
    cudaGetSymbolAddress((void**)&v_p,    d_v);
    cudaGetSymbolAddress((void**)&g1_p,   d_g1);
    cudaGetSymbolAddress((void**)&gate_p, d_gate);
    cudaGetSymbolAddress((void**)&kc_p,   d_kc);
    cudaGetSymbolAddress((void**)&vc_p,   d_vc);
    cudaGetSymbolAddress((void**)&o1_p,   d_o1);
    cudaGetSymbolAddress((void**)&o2_p,   d_o2);
    cudaGetSymbolAddress((void**)&o3_p,   d_o3);

    const float scale = 0.125f;

    cudaEventRecord(e0, 0);
    cudaStreamWaitEvent(sA, e0, 0);

    // stream0: fused QKV projection
    gemm_big<<<dim3(8,16,3),256>>>(x, nullptr, nullptr, wq, wk, wv,
                                   q_p, k_p, v_p, S, 1024, DIMM, EPI_HEAD);
    cudaEventRecord(e_qkv, 0);

    // sA: gate chain
    gemm_big<<<dim3(4,16,1),256,0,sA>>>(x, nullptr, nullptr, gw1, gw1, gw1,
                                        g1_p, g1_p, g1_p, S, 512, DIMM, EPI_SILU);
    gemm_big<<<dim3(1,16,1),256,0,sA>>>(g1_p, nullptr, nullptr, gw2, gw2, gw2,
                                        gate_p, gate_p, gate_p, S, GDIM, 512, EPI_SIGMOID);
    cudaEventRecord(e_gate, sA);

    // stream0: fused K+V compression, then compressed branch (+ masks)
    compress2<<<dim3(32,16,2),256>>>(k_p, v_p, pe_k, down_k, stop_k,
                                     pe_v, down_v, stop_v, kc_p, vc_p);
    cudaStreamWaitEvent(0, e_gate, 0);
    cmp_attn<<<dim3(S/8,16),128,CSM>>>(scale);
    cudaEventRecord(e_cmp, 0);

    // sA: sliding-window branch
    cudaStreamWaitEvent(sA, e_qkv, 0);
    attn_flash<1><<<dim3(S/64,16),256,FSM,sA>>>(scale);
    cudaEventRecord(e_f1, sA);

    // sB: selection branch (needs masks + gate)
    cudaStreamWaitEvent(sB, e_cmp, 0);
    cudaStreamWaitEvent(sB, e_gate, 0);
    attn_flash<0><<<dim3(S/64,16),256,FSM,sB>>>(scale);
    cudaEventRecord(e_f0, sB);

    // join + output projection
    cudaStreamWaitEvent(0, e_f1, 0);
    cudaStreamWaitEvent(0, e_f0, 0);
    gemm_big<<<dim3(8,16,1),256>>>(o1_p, o2_p, o3_p, wo, wo, wo,
                                   (float*)d_out, (float*)d_out, (float*)d_out,
                                   S, DIMM, DIMM, EPI_NONE);
}

// round 7
// speedup vs baseline: 1.1884x; 1.1416x over previous
#include <cuda_runtime.h>
#include <math.h>

#define H    16
#define S    2048
#define D    64
#define DIMM 1024
#define SCMP 128
#define GDIM 48

#define BK 16
#define ASTR 132   // smem row stride (words) for GEMM tiles

#define ST 68      // shared row stride (floats) for flash tiles

// ---------------- scratch ----------------
__device__ float d_q[H*S*D];
__device__ float d_k[H*S*D];
__device__ float d_v[H*S*D];
__device__ float d_g1[S*512];
__device__ float d_gate[S*GDIM];
__device__ float d_kc[H*SCMP*D];
__device__ float d_vc[H*SCMP*D];
__device__ float d_o1[S*DIMM];
__device__ float d_o2[S*DIMM];
__device__ float d_o3[S*DIMM];
__device__ unsigned d_bm[H*S];

enum { EPI_NONE=0, EPI_SILU=1, EPI_SIGMOID=2, EPI_HEAD=3 };

__device__ __forceinline__ unsigned f2tf(float x){
    unsigned r; asm("cvt.rna.tf32.f32 %0, %1;" : "=r"(r) : "f"(x)); return r;
}
__device__ __forceinline__ void mma_tf32(float* c, const unsigned* a, const unsigned* b){
    asm volatile("mma.sync.aligned.m16n8k8.row.col.f32.tf32.tf32.f32 "
        "{%0,%1,%2,%3}, {%4,%5,%6,%7}, {%8,%9}, {%0,%1,%2,%3};"
        : "+f"(c[0]),"+f"(c[1]),"+f"(c[2]),"+f"(c[3])
        : "r"(a[0]),"r"(a[1]),"r"(a[2]),"r"(a[3]), "r"(b[0]),"r"(b[1]));
}

// ---------------- tf32x3 tensor-core GEMM ----------------
// C = epi(A @ B). A:[M,K] (optionally A+Ab+Ac on load), B:[K,N].
// blockIdx.z selects (B,C). Tile 128x128xBK16, 256 thr (8 warps, 2x4 warp grid,
// warp tile 64x32 via 4x4 m16n8k8 mma). hi/lo tf32 split at smem store.
// Requires M%128==0, K%16==0, N%4==0.
__global__ __launch_bounds__(256)
void gemm_tc(const float* __restrict__ A,
             const float* __restrict__ Ab,
             const float* __restrict__ Ac,
             const float* __restrict__ B0,
             const float* __restrict__ B1,
             const float* __restrict__ B2,
             float* __restrict__ C0,
             float* __restrict__ C1,
             float* __restrict__ C2,
             int M, int N, int K, int epi)
{
    extern __shared__ unsigned gsm[];
    const int TB = BK*ASTR;          // words per (buf) plane
    unsigned* AH = gsm;              // [2][BK][ASTR]
    unsigned* AL = AH + 2*TB;
    unsigned* BH = AL + 2*TB;
    unsigned* BL = BH + 2*TB;

    const int tid = threadIdx.x;
    const int wid = tid >> 5, lane = tid & 31;
    const int wm = wid >> 2, wn = wid & 3;
    const int g = lane >> 2, tig = lane & 3;
    const int m0 = blockIdx.y*128, n0 = blockIdx.x*128;
    const float* B = blockIdx.z==0 ? B0 : (blockIdx.z==1 ? B1 : B2);
    float* C = blockIdx.z==0 ? C0 : (blockIdx.z==1 ? C1 : C2);

    const int arow = tid & 127;      // A: m index, float4 along k
    const int akq  = tid >> 7;       // 0..1 -> k-quads {akq, akq+2}
    const int bkk  = tid >> 5;       // 0..7 -> k rows {bkk, bkk+8}
    const int bn   = (tid & 31)*4;   // B: n start, float4 along n
    const long abase = (long)(m0 + arow)*K;
    const bool bok = (n0 + bn) < N;

    float acc[16][4];
    #pragma unroll
    for (int i=0;i<16;i++){ acc[i][0]=0.f; acc[i][1]=0.f; acc[i][2]=0.f; acc[i][3]=0.f; }

    const int nT = K/BK;
    float4 ra[2], rb[2];

    // prologue
    #pragma unroll
    for (int i=0;i<2;i++){
        long off = abase + (akq + i*2)*4;
        float4 v = *(const float4*)(A + off);
        if (Ab){
            float4 w = *(const float4*)(Ab + off);
            float4 u = *(const float4*)(Ac + off);
            v.x+=w.x+u.x; v.y+=w.y+u.y; v.z+=w.z+u.z; v.w+=w.w+u.w;
        }
        ra[i]=v;
        rb[i]= bok ? *(const float4*)(B + (long)(bkk + i*8)*N + n0 + bn)
                   : make_float4(0.f,0.f,0.f,0.f);
    }
    #pragma unroll
    for (int i=0;i<2;i++){
        int kq=(akq+i*2)*4;
        float av[4]={ra[i].x,ra[i].y,ra[i].z,ra[i].w};
        #pragma unroll
        for (int c=0;c<4;c++){
            unsigned hi = f2tf(av[c]);
            AH[(kq+c)*ASTR + arow] = hi;
            AL[(kq+c)*ASTR + arow] = f2tf(av[c] - __uint_as_float(hi));
        }
        float bv[4]={rb[i].x,rb[i].y,rb[i].z,rb[i].w};
        int krow = bkk + i*8;
        #pragma unroll
        for (int c=0;c<4;c++){
            unsigned hi = f2tf(bv[c]);
            BH[krow*ASTR + bn + c] = hi;
            BL[krow*ASTR + bn + c] = f2tf(bv[c] - __uint_as_float(hi));
        }
    }
    __syncthreads();

    int buf=0;
    for (int t=0;t<nT;t++){
        if (t+1<nT){
            int k0=(t+1)*BK;
            #pragma unroll
            for (int i=0;i<2;i++){
                long off = abase + k0 + (akq + i*2)*4;
                float4 v = *(const float4*)(A + off);
                if (Ab){
                    float4 w = *(const float4*)(Ab + off);
                    float4 u = *(const float4*)(Ac + off);
                    v.x+=w.x+u.x; v.y+=w.y+u.y; v.z+=w.z+u.z; v.w+=w.w+u.w;
                }
                ra[i]=v;
                rb[i]= bok ? *(const float4*)(B + (long)(k0 + bkk + i*8)*N + n0 + bn)
                           : make_float4(0.f,0.f,0.f,0.f);
            }
        }
        {
            const unsigned* Ah = AH + buf*TB;
            const unsigned* Al = AL + buf*TB;
            const unsigned* Bh = BH + buf*TB;
            const unsigned* Bl = BL + buf*TB;
            #pragma unroll
            for (int kc=0;kc<BK;kc+=8){
                unsigned aF[16], bF[8], bL2[8];
                #pragma unroll
                for (int i=0;i<4;i++){
                    int m = wm*64 + i*16 + g;
                    aF[i*4+0] = Ah[(kc+tig)*ASTR + m];
                    aF[i*4+1] = Ah[(kc+tig)*ASTR + m+8];
                    aF[i*4+2] = Ah[(kc+tig+4)*ASTR + m];
                    aF[i*4+3] = Ah[(kc+tig+4)*ASTR + m+8];
                }
                #pragma unroll
                for (int j=0;j<4;j++){
                    int n = wn*32 + j*8 + g;
                    bF[j*2+0] = Bh[(kc+tig)*ASTR + n];
                    bF[j*2+1] = Bh[(kc+tig+4)*ASTR + n];
                }
                #pragma unroll
                for (int i=0;i<4;i++)
                    #pragma unroll
                    for (int j=0;j<4;j++) mma_tf32(acc[i*4+j], &aF[i*4], &bF[j*2]);
                #pragma unroll
                for (int j=0;j<4;j++){
                    int n = wn*32 + j*8 + g;
                    bL2[j*2+0] = Bl[(kc+tig)*ASTR + n];
                    bL2[j*2+1] = Bl[(kc+tig+4)*ASTR + n];
                }
                #pragma unroll
                for (int i=0;i<4;i++)
                    #pragma unroll
                    for (int j=0;j<4;j++) mma_tf32(acc[i*4+j], &aF[i*4], &bL2[j*2]);
                #pragma unroll
                for (int i=0;i<4;i++){
                    int m = wm*64 + i*16 + g;
                    aF[i*4+0] = Al[(kc+tig)*ASTR + m];
                    aF[i*4+1] = Al[(kc+tig)*ASTR + m+8];
                    aF[i*4+2] = Al[(kc+tig+4)*ASTR + m];
                    aF[i*4+3] = Al[(kc+tig+4)*ASTR + m+8];
                }
                #pragma unroll
                for (int i=0;i<4;i++)
                    #pragma unroll
                    for (int j=0;j<4;j++) mma_tf32(acc[i*4+j], &aF[i*4], &bF[j*2]);
            }
        }
        if (t+1<nT){
            int nb=buf^1;
            #pragma unroll
            for (int i=0;i<2;i++){
                int kq=(akq+i*2)*4;
                float av[4]={ra[i].x,ra[i].y,ra[i].z,ra[i].w};
                #pragma unroll
                for (int c=0;c<4;c++){
                    unsigned hi = f2tf(av[c]);
                    AH[nb*TB + (kq+c)*ASTR + arow] = hi;
                    AL[nb*TB + (kq+c)*ASTR + arow] = f2tf(av[c] - __uint_as_float(hi));
                }
                float bv[4]={rb[i].x,rb[i].y,rb[i].z,rb[i].w};
                int krow = bkk + i*8;
                #pragma unroll
                for (int c=0;c<4;c++){
                    unsigned hi = f2tf(bv[c]);
                    BH[nb*TB + krow*ASTR + bn + c] = hi;
                    BL[nb*TB + krow*ASTR + bn + c] = f2tf(bv[c] - __uint_as_float(hi));
                }
            }
        }
        __syncthreads();
        buf^=1;
    }

    // epilogue
    #pragma unroll
    for (int i=0;i<4;i++){
        #pragma unroll
        for (int j=0;j<4;j++){
            const float* c = acc[i*4+j];
            int rowb = m0 + wm*64 + i*16 + g;
            int colb = n0 + wn*32 + j*8 + 2*tig;
            #pragma unroll
            for (int e=0;e<4;e++){
                int gm = rowb + (e>=2 ? 8 : 0);
                int gn = colb + (e&1);
                if (gn >= N) continue;
                float vv = c[e];
                if (epi==EPI_SILU)         vv = vv/(1.f+__expf(-vv));
                else if (epi==EPI_SIGMOID) vv = 1.f/(1.f+__expf(-vv));
                if (epi==EPI_HEAD) C[((gn>>6)*S + gm)*D + (gn&63)] = vv;
                else               C[(long)gm*N + gn] = vv;
            }
        }
    }
}

// ---------------- compression Phi ----------------
template<int P>
__device__ __forceinline__ void phi_level(const float* __restrict__ a,
                                          float* __restrict__ b,
                                          const float* __restrict__ W, int d)
{
    float accs[P];
    #pragma unroll
    for (int p=0;p<P;p++) accs[p]=0.f;
    #pragma unroll 4
    for (int j=0;j<128;j+=4){
        float w0=W[(j+0)*64+d], w1=W[(j+1)*64+d];
        float w2=W[(j+2)*64+d], w3=W[(j+3)*64+d];
        #pragma unroll
        for (int p=0;p<P;p++){
            float4 c = *(const float4*)&a[p*128+j];
            accs[p] += c.x*w0;
            accs[p] += c.y*w1;
            accs[p] += c.z*w2;
            accs[p] += c.w*w3;
        }
    }
    #pragma unroll
    for (int p=0;p<P;p++){
        float xx = accs[p];
        b[p*64+d] = xx / (1.f + __expf(-xx));
    }
}

__global__ __launch_bounds__(256)
void compress2(const float* __restrict__ ksrc, const float* __restrict__ vsrc,
               const float* __restrict__ pe_k, const float* __restrict__ down_k,
               const float* __restrict__ stop_k,
               const float* __restrict__ pe_v, const float* __restrict__ down_v,
               const float* __restrict__ stop_v,
               float* __restrict__ kc, float* __restrict__ vc)
{
    __shared__ __align__(16) float bufX[4*2048];
    __shared__ __align__(16) float bufY[4*1024];
    const int tid = threadIdx.x;
    const int d   = tid & 63;
    const int sub = tid >> 6;
    const int w   = blockIdx.x*4 + sub;
    const int h   = blockIdx.y;
    const int z   = blockIdx.z;
    const float* src  = z ? vsrc  : ksrc;
    const float* pe   = z ? pe_v  : pe_k;
    const float* down = z ? down_v: down_k;
    const float* stop = z ? stop_v: stop_k;
    float* dst        = z ? vc    : kc;

    float* X = bufX + sub*2048;
    float* Y = bufY + sub*1024;

    if (w > 0){
        int s0 = (w-1)*16;
        #pragma unroll
        for (int i=0;i<32;i++)
            X[i*64+d] = src[(h*S + s0+i)*D + d] + pe[i*64+d];
    }
    __syncthreads();

    phi_level<16>(X, Y, down,         d);  __syncthreads();
    phi_level<8> (Y, X, down + 8192,  d);  __syncthreads();
    phi_level<4> (X, Y, down + 16384, d);  __syncthreads();
    phi_level<2> (Y, X, down + 24576, d);  __syncthreads();
    phi_level<1> (X, Y, down + 32768, d);  __syncthreads();

    float a = 0.f;
    #pragma unroll
    for (int j=0;j<64;j+=4){
        float4 c = *(const float4*)&Y[j];
        a += c.x*stop[(j+0)*64+d];
        a += c.y*stop[(j+1)*64+d];
        a += c.z*stop[(j+2)*64+d];
        a += c.w*stop[(j+3)*64+d];
    }
    dst[(h*SCMP + w)*D + d] = (w > 0) ? a : 0.f;
}

// ---------------- compressed branch + conv + top-k selection ----------------
// kc_s row stride 65 -> conflict-free QK loads
__global__ void cmp_attn(float scale)
{
    extern __shared__ float csm[];
    float* kc_s = csm;               // 128*65
    float* vc_s = kc_s + 128*65;     // 8192
    float* q_s  = vc_s + 8192;       // 64
    float* p_sm = q_s + 64;          // 128
    float* ps   = p_sm + 128;        // 32
    float* ps2  = ps + 32;           // 64
    float* red  = ps2 + 64;          // 4

    int h = blockIdx.y;
    int tid = threadIdx.x;
    int lane = tid & 31, wid = tid >> 5;

    for (int i=tid;i<8192;i+=128){
        kc_s[(i>>6)*65 + (i&63)] = d_kc[h*8192+i];
        vc_s[i] = d_vc[h*8192+i];
    }

    for (int qi=0;qi<8;qi++){
        int q = blockIdx.x*8 + qi;
        __syncthreads();
        if (tid < 64) q_s[tid] = d_q[(h*S + q)*D + tid];
        __syncthreads();

        int r = q >> 4;
        float sc = -INFINITY;
        {
            bool ok = (tid <= r-1) || (tid==0 && r<32);
            if (ok){
                float a=0.f;
                #pragma unroll
                for (int dd=0;dd<64;dd++) a += q_s[dd]*kc_s[tid*65+dd];
                sc = a*scale;
            }
        }
        float v = sc;
        #pragma unroll
        for (int off=16;off;off>>=1) v = fmaxf(v, __shfl_xor_sync(0xffffffffu,v,off));
        if (lane==0) red[wid]=v;
        __syncthreads();
        float m = fmaxf(fmaxf(red[0],red[1]),fmaxf(red[2],red[3]));
        float p = __expf(sc - m);
        p_sm[tid] = p;
        __syncthreads();
        float sv = p;
        #pragma unroll
        for (int off=16;off;off>>=1) sv += __shfl_xor_sync(0xffffffffu,sv,off);
        if (lane==0) red[wid]=sv;
        __syncthreads();
        float l = red[0]+red[1]+red[2]+red[3];

        if (wid == 3){
            int n = lane;
            float a = 2.f*(p_sm[4*n] + p_sm[4*n+1] + p_sm[4*n+2]) + p_sm[4*n+3];
            if (4*n-1 >= 0) a += p_sm[4*n-1];
            ps[n] = a;
            __syncwarp();
            float mv = ps[n];
            int cnt = 0;
            #pragma unroll
            for (int i2=0;i2<32;i2++){
                float vi = ps[i2];
                cnt += (vi > mv) || (vi == mv && i2 < n);
            }
            bool sel = (cnt < 16) && (n < (q >> 6));
            unsigned msk = __ballot_sync(0xffffffffu, sel);
            if (lane==0) d_bm[h*S + q] = msk;
        }
        float a;
        if (tid < 64){
            a = 0.f;
            for (int j=0;j<64;j++) a += p_sm[j]*vc_s[j*64+tid];
        } else {
            float b = 0.f;
            int dd = tid - 64;
            for (int j=64;j<128;j++) b += p_sm[j]*vc_s[j*64+dd];
            ps2[dd] = b;
            a = 0.f;
        }
        __syncthreads();
        if (tid < 64){
            float g0 = d_gate[q*GDIM + h*3 + 0];
            d_o1[q*DIMM + h*64 + tid] = g0 * ((a + ps2[tid]) / l);
        }
    }
}

// ---------------- flash-style sparse attention (float4-vectorized) ----------------
template<int MODE>
__global__ __launch_bounds__(256) void attn_flash(float scale)
{
    extern __shared__ float fsm[];
    float* q_s  = fsm;
    float* kT_s = q_s  + 64*ST;
    float* v_s  = kT_s + 64*ST;
    float* p_s  = v_s  + 64*ST;
    float* m_s  = p_s  + 64*ST;
    float* l_s  = m_s + 64;
    unsigned* msk_s = (unsigned*)(l_s + 64);
    unsigned* u_s   = msk_s + 64;

    int tq = blockIdx.x, h = blockIdx.y;
    int q0 = tq*64;
    int tid = threadIdx.x;
    int tx = tid & 15, ty = tid >> 4;

    #pragma unroll
    for (int r2=0;r2<4;r2++){
        int li = tid + r2*256;
        int row = li >> 4, c4 = (li & 15)*4;
        *(float4*)&q_s[row*ST + c4] = *(const float4*)&d_q[(h*S + q0+row)*D + c4];
    }
    if (tid < 64){
        m_s[tid] = -INFINITY; l_s[tid] = 0.f;
        if (MODE==0) msk_s[tid] = d_bm[h*S + q0 + tid];
    }
    __syncthreads();

    unsigned uni = 0xFFFFFFFFu;
    if (MODE==0){
        if (tid==0){
            unsigned u=0;
            for (int i=0;i<64;i++) u |= msk_s[i];
            u_s[0]=u;
        }
        __syncthreads();
        uni = u_s[0];
    }

    int nlo, nhi;
    if (MODE==0){ nlo=0; nhi=(uni==0u)?0:tq; }
    else { nlo = tq-8; if (nlo<0) nlo=0; nhi = tq+1; }

    float acc[4][4];
    #pragma unroll
    for (int i=0;i<4;i++)
        #pragma unroll
        for (int j=0;j<4;j++) acc[i][j]=0.f;

    for (int n=nlo;n<nhi;n++){
        if (MODE==0 && !((uni>>n)&1u)) continue;

        #pragma unroll
        for (int r2=0;r2<4;r2++){
            int li = tid + r2*256;
            int row = li >> 4, c4 = (li & 15)*4;
            float4 kv = *(const float4*)&d_k[(h*S + n*64+row)*D + c4];
            kT_s[(c4+0)*ST + row] = kv.x;
            kT_s[(c4+1)*ST + row] = kv.y;
            kT_s[(c4+2)*ST + row] = kv.z;
            kT_s[(c4+3)*ST + row] = kv.w;
            *(float4*)&v_s[row*ST + c4] = *(const float4*)&d_v[(h*S + n*64+row)*D + c4];
        }
        __syncthreads();

        float s[4][4];
        #pragma unroll
        for (int i=0;i<4;i++)
            #pragma unroll
            for (int j=0;j<4;j++) s[i][j]=0.f;
        #pragma unroll
        for (int dd=0;dd<64;dd+=4){
            float4 qv[4], kv[4];
            #pragma unroll
            for (int i=0;i<4;i++) qv[i] = *(const float4*)&q_s[(ty*4+i)*ST + dd];
            #pragma unroll
            for (int c=0;c<4;c++) kv[c] = *(const float4*)&kT_s[(dd+c)*ST + tx*4];
            #pragma unroll
            for (int i=0;i<4;i++){
                s[i][0] += qv[i].x*kv[0].x + qv[i].y*kv[1].x + qv[i].z*kv[2].x + qv[i].w*kv[3].x;
                s[i][1] += qv[i].x*kv[0].y + qv[i].y*kv[1].y + qv[i].z*kv[2].y + qv[i].w*kv[3].y;
                s[i][2] += qv[i].x*kv[0].z + qv[i].y*kv[1].z + qv[i].z*kv[2].z + qv[i].w*kv[3].z;
                s[i][3] += qv[i].x*kv[0].w + qv[i].y*kv[1].w + qv[i].z*kv[2].w + qv[i].w*kv[3].w;
            }
        }

        float amn[4], anl[4];
        #pragma unroll
        for (int i=0;i<4;i++){
            int qi = ty*4+i;
            int qg = q0 + qi;
            unsigned mbits = (MODE==0) ? msk_s[qi] : 0u;
            float rm = -INFINITY;
            #pragma unroll
            for (int j=0;j<4;j++){
                bool ok;
                if (MODE==0) ok = (mbits>>n)&1u;
                else { int t = n*64 + tx*4 + j; ok = (t <= qg) && (qg - t <= 512); }
                float val = ok ? s[i][j]*scale : -INFINITY;
                s[i][j]=val;
                rm = fmaxf(rm, val);
            }
            #pragma unroll
            for (int off=8;off;off>>=1) rm = fmaxf(rm, __shfl_xor_sync(0xffffffffu, rm, off));
            float mo = m_s[qi];
            float mn = fmaxf(mo, rm);
            float alpha = 1.f, ts = 0.f;
            if (mn == -INFINITY){
                #pragma unroll
                for (int j=0;j<4;j++) s[i][j]=0.f;
            } else {
                alpha = __expf(mo - mn);
                #pragma unroll
                for (int j=0;j<4;j++){ float pp = __expf(s[i][j]-mn); s[i][j]=pp; ts += pp; }
            }
            #pragma unroll
            for (int off=8;off;off>>=1) ts += __shfl_xor_sync(0xffffffffu, ts, off);
            *(float4*)&p_s[qi*ST + tx*4] = make_float4(s[i][0],s[i][1],s[i][2],s[i][3]);
            #pragma unroll
            for (int j=0;j<4;j++) acc[i][j] *= alpha;
            amn[i]=mn; anl[i]=l_s[qi]*alpha + ts;
        }
        __syncthreads();
        if (tx==0){
            #pragma unroll
            for (int i=0;i<4;i++){ m_s[ty*4+i]=amn[i]; l_s[ty*4+i]=anl[i]; }
        }

        #pragma unroll
        for (int kk=0;kk<64;kk+=4){
            float4 pv[4], vv[4];
            #pragma unroll
            for (int i=0;i<4;i++) pv[i] = *(const float4*)&p_s[(ty*4+i)*ST + kk];
            #pragma unroll
            for (int c=0;c<4;c++) vv[c] = *(const float4*)&v_s[(kk+c)*ST + tx*4];
            #pragma unroll
            for (int i=0;i<4;i++){
                acc[i][0] += pv[i].x*vv[0].x + pv[i].y*vv[1].x + pv[i].z*vv[2].x + pv[i].w*vv[3].x;
                acc[i][1] += pv[i].x*vv[0].y + pv[i].y*vv[1].y + pv[i].z*vv[2].y + pv[i].w*vv[3].y;
                acc[i][2] += pv[i].x*vv[0].z + pv[i].y*vv[1].z + pv[i].z*vv[2].z + pv[i].w*vv[3].z;
                acc[i][3] += pv[i].x*vv[0].w + pv[i].y*vv[1].w + pv[i].z*vv[2].w + pv[i].w*vv[3].w;
            }
        }
        __syncthreads();
    }

    float* outp = (MODE==0) ? d_o2 : d_o3;
    #pragma unroll
    for (int i=0;i<4;i++){
        int qg = q0 + ty*4 + i;
        float l = l_s[ty*4+i];
        float inv = (l > 0.f) ? 1.f/l : 0.f;
        float g = d_gate[qg*GDIM + h*3 + (MODE==0 ? 1 : 2)];
        #pragma unroll
        for (int j=0;j<4;j++)
            outp[qg*DIMM + h*64 + tx*4 + j] = g * acc[i][j] * inv;
    }
}

// ---------------- launch ----------------
static cudaStream_t sA = nullptr, sB = nullptr;
static cudaEvent_t e0, e_qkv, e_gate, e_cmp, e_f0, e_f1;

extern "C" void kernel_launch(void* const* d_in, const int* in_sizes, int n_in,
                              void* d_out, int out_size)
{
    (void)in_sizes; (void)n_in; (void)out_size;
    const float* x      = (const float*)d_in[0];
    const float* wq     = (const float*)d_in[1];
    const float* wk     = (const float*)d_in[2];
    const float* wv     = (const float*)d_in[3];
    const float* wo     = (const float*)d_in[4];
    const float* gw1    = (const float*)d_in[5];
    const float* gw2    = (const float*)d_in[6];
    const float* pe_k   = (const float*)d_in[7];
    const float* down_k = (const float*)d_in[8];
    const float* stop_k = (const float*)d_in[9];
    const float* pe_v   = (const float*)d_in[10];
    const float* down_v = (const float*)d_in[11];
    const float* stop_v = (const float*)d_in[12];

    const int GSM = 4*2*BK*ASTR*4;                       // 67584 B
    const int CSM = (128*65 + 8192 + 64+128+32+64+4)*4;
    const int FSM = (4*64*ST + 64 + 64)*4 + 64*4 + 16;

    if (!sA){
        cudaStreamCreateWithFlags(&sA, cudaStreamNonBlocking);
        cudaStreamCreateWithFlags(&sB, cudaStreamNonBlocking);
        cudaEventCreateWithFlags(&e0,     cudaEventDisableTiming);
        cudaEventCreateWithFlags(&e_qkv,  cudaEventDisableTiming);
        cudaEventCreateWithFlags(&e_gate, cudaEventDisableTiming);
        cudaEventCreateWithFlags(&e_cmp,  cudaEventDisableTiming);
        cudaEventCreateWithFlags(&e_f0,   cudaEventDisableTiming);
        cudaEventCreateWithFlags(&e_f1,   cudaEventDisableTiming);
        cudaFuncSetAttribute(gemm_tc,  cudaFuncAttributeMaxDynamicSharedMemorySize, GSM);
        cudaFuncSetAttribute(cmp_attn, cudaFuncAttributeMaxDynamicSharedMemorySize, CSM);
        cudaFuncSetAttribute(attn_flash<0>, cudaFuncAttributeMaxDynamicSharedMemorySize, FSM);
        cudaFuncSetAttribute(attn_flash<1>, cudaFuncAttributeMaxDynamicSharedMemorySize, FSM);
    }

    float *q_p, *k_p, *v_p, *g1_p, *gate_p, *kc_p, *vc_p, *o1_p, *o2_p, *o3_p;
    cudaGetSymbolAddress((void**)&q_p,    d_q);
    cudaGetSymbolAddress((void**)&k_p,    d_k);
    cudaGetSymbolAddress((void**)&v_p,    d_v);
    cudaGetSymbolAddress((void**)&g1_p,   d_g1);
    cudaGetSymbolAddress((void**)&gate_p, d_gate);
    cudaGetSymbolAddress((void**)&kc_p,   d_kc);
    cudaGetSymbolAddress((void**)&vc_p,   d_vc);
    cudaGetSymbolAddress((void**)&o1_p,   d_o1);
    cudaGetSymbolAddress((void**)&o2_p,   d_o2);
    cudaGetSymbolAddress((void**)&o3_p,   d_o3);

    const float scale = 0.125f;

    cudaEventRecord(e0, 0);
    cudaStreamWaitEvent(sA, e0, 0);

    // stream0: fused QKV projection (tf32x3 tensor cores)
    gemm_tc<<<dim3(8,16,3),256,GSM>>>(x, nullptr, nullptr, wq, wk, wv,
                                      q_p, k_p, v_p, S, 1024, DIMM, EPI_HEAD);
    cudaEventRecord(e_qkv, 0);

    // sA: gate chain
    gemm_tc<<<dim3(4,16,1),256,GSM,sA>>>(x, nullptr, nullptr, gw1, gw1, gw1,
                                         g1_p, g1_p, g1_p, S, 512, DIMM, EPI_SILU);
    gemm_tc<<<dim3(1,16,1),256,GSM,sA>>>(g1_p, nullptr, nullptr, gw2, gw2, gw2,
                                         gate_p, gate_p, gate_p, S, GDIM, 512, EPI_SIGMOID);
    cudaEventRecord(e_gate, sA);

    // stream0: fused K+V compression, then compressed branch (+ masks)
    compress2<<<dim3(32,16,2),256>>>(k_p, v_p, pe_k, down_k, stop_k,
                                     pe_v, down_v, stop_v, kc_p, vc_p);
    cudaStreamWaitEvent(0, e_gate, 0);
    cmp_attn<<<dim3(S/8,16),128,CSM>>>(scale);
    cudaEventRecord(e_cmp, 0);

    // sA: sliding-window branch
    cudaStreamWaitEvent(sA, e_qkv, 0);
    attn_flash<1><<<dim3(S/64,16),256,FSM,sA>>>(scale);
    cudaEventRecord(e_f1, sA);

    // sB: selection branch (needs masks + gate)
    cudaStreamWaitEvent(sB, e_cmp, 0);
    cudaStreamWaitEvent(sB, e_gate, 0);
    attn_flash<0><<<dim3(S/64,16),256,FSM,sB>>>(scale);
    cudaEventRecord(e_f0, sB);

    // join + output projection
    cudaStreamWaitEvent(0, e_f1, 0);
    cudaStreamWaitEvent(0, e_f0, 0);
    gemm_tc<<<dim3(8,16,1),256,GSM>>>(o1_p, o2_p, o3_p, wo, wo, wo,
                                      (float*)d_out, (float*)d_out, (float*)d_out,
                                      S, DIMM, DIMM, EPI_NONE);
}

// round 8
// speedup vs baseline: 1.2937x; 1.0886x over previous
#include <cuda_runtime.h>
#include <math.h>

#define H    16
#define S    2048
#define D    64
#define DIMM 1024
#define SCMP 128
#define GDIM 48

#define BK 16
#define ASTR 132   // smem row stride (words) for GEMM tiles
#define PS   68    // smem row stride (floats) for flash planes

// ---------------- scratch ----------------
__device__ float d_q[H*S*D];
__device__ float d_k[H*S*D];
__device__ float d_v[H*S*D];
__device__ float d_g1[S*512];
__device__ float d_gate[S*GDIM];
__device__ float d_kc[H*SCMP*D];
__device__ float d_vc[H*SCMP*D];
__device__ float d_o1[S*DIMM];
__device__ float d_o2[S*DIMM];
__device__ float d_o3[S*DIMM];
__device__ unsigned d_bm[H*S];

enum { EPI_NONE=0, EPI_SILU=1, EPI_SIGMOID=2, EPI_HEAD=3 };

__device__ __forceinline__ unsigned f2tf(float x){
    unsigned r; asm("cvt.rna.tf32.f32 %0, %1;" : "=r"(r) : "f"(x)); return r;
}
__device__ __forceinline__ void mma_tf32(float* c, const unsigned* a, const unsigned* b){
    asm volatile("mma.sync.aligned.m16n8k8.row.col.f32.tf32.tf32.f32 "
        "{%0,%1,%2,%3}, {%4,%5,%6,%7}, {%8,%9}, {%0,%1,%2,%3};"
        : "+f"(c[0]),"+f"(c[1]),"+f"(c[2]),"+f"(c[3])
        : "r"(a[0]),"r"(a[1]),"r"(a[2]),"r"(a[3]), "r"(b[0]),"r"(b[1]));
}
// split fp32 -> (hi,lo) tf32 pair
__device__ __forceinline__ void tfsplit(float x, unsigned& hi, unsigned& lo){
    hi = f2tf(x);
    lo = f2tf(x - __uint_as_float(hi));
}

// ---------------- tf32x3 tensor-core GEMM ----------------
__global__ __launch_bounds__(256)
void gemm_tc(const float* __restrict__ A,
             const float* __restrict__ Ab,
             const float* __restrict__ Ac,
             const float* __restrict__ B0,
             const float* __restrict__ B1,
             const float* __restrict__ B2,
             float* __restrict__ C0,
             float* __restrict__ C1,
             float* __restrict__ C2,
             int M, int N, int K, int epi)
{
    extern __shared__ unsigned gsm[];
    const int TB = BK*ASTR;
    unsigned* AH = gsm;
    unsigned* AL = AH + 2*TB;
    unsigned* BH = AL + 2*TB;
    unsigned* BL = BH + 2*TB;

    const int tid = threadIdx.x;
    const int wid = tid >> 5, lane = tid & 31;
    const int wm = wid >> 2, wn = wid & 3;
    const int g = lane >> 2, tig = lane & 3;
    const int m0 = blockIdx.y*128, n0 = blockIdx.x*128;
    const float* B = blockIdx.z==0 ? B0 : (blockIdx.z==1 ? B1 : B2);
    float* C = blockIdx.z==0 ? C0 : (blockIdx.z==1 ? C1 : C2);

    const int arow = tid & 127;
    const int akq  = tid >> 7;
    const int bkk  = tid >> 5;
    const int bn   = (tid & 31)*4;
    const long abase = (long)(m0 + arow)*K;
    const bool bok = (n0 + bn) < N;

    float acc[16][4];
    #pragma unroll
    for (int i=0;i<16;i++){ acc[i][0]=0.f; acc[i][1]=0.f; acc[i][2]=0.f; acc[i][3]=0.f; }

    const int nT = K/BK;
    float4 ra[2], rb[2];

    #pragma unroll
    for (int i=0;i<2;i++){
        long off = abase + (akq + i*2)*4;
        float4 v = *(const float4*)(A + off);
        if (Ab){
            float4 w = *(const float4*)(Ab + off);
            float4 u = *(const float4*)(Ac + off);
            v.x+=w.x+u.x; v.y+=w.y+u.y; v.z+=w.z+u.z; v.w+=w.w+u.w;
        }
        ra[i]=v;
        rb[i]= bok ? *(const float4*)(B + (long)(bkk + i*8)*N + n0 + bn)
                   : make_float4(0.f,0.f,0.f,0.f);
    }
    #pragma unroll
    for (int i=0;i<2;i++){
        int kq=(akq+i*2)*4;
        float av[4]={ra[i].x,ra[i].y,ra[i].z,ra[i].w};
        #pragma unroll
        for (int c=0;c<4;c++){
            unsigned hi,lo; tfsplit(av[c],hi,lo);
            AH[(kq+c)*ASTR + arow] = hi;
            AL[(kq+c)*ASTR + arow] = lo;
        }
        float bv[4]={rb[i].x,rb[i].y,rb[i].z,rb[i].w};
        int krow = bkk + i*8;
        #pragma unroll
        for (int c=0;c<4;c++){
            unsigned hi,lo; tfsplit(bv[c],hi,lo);
            BH[krow*ASTR + bn + c] = hi;
            BL[krow*ASTR + bn + c] = lo;
        }
    }
    __syncthreads();

    int buf=0;
    for (int t=0;t<nT;t++){
        if (t+1<nT){
            int k0=(t+1)*BK;
            #pragma unroll
            for (int i=0;i<2;i++){
                long off = abase + k0 + (akq + i*2)*4;
                float4 v = *(const float4*)(A + off);
                if (Ab){
                    float4 w = *(const float4*)(Ab + off);
                    float4 u = *(const float4*)(Ac + off);
                    v.x+=w.x+u.x; v.y+=w.y+u.y; v.z+=w.z+u.z; v.w+=w.w+u.w;
                }
                ra[i]=v;
                rb[i]= bok ? *(const float4*)(B + (long)(k0 + bkk + i*8)*N + n0 + bn)
                           : make_float4(0.f,0.f,0.f,0.f);
            }
        }
        {
            const unsigned* Ah = AH + buf*TB;
            const unsigned* Al = AL + buf*TB;
            const unsigned* Bh = BH + buf*TB;
            const unsigned* Bl = BL + buf*TB;
            #pragma unroll
            for (int kc=0;kc<BK;kc+=8){
                unsigned aF[16], bF[8], bL2[8];
                #pragma unroll
                for (int i=0;i<4;i++){
                    int m = wm*64 + i*16 + g;
                    aF[i*4+0] = Ah[(kc+tig)*ASTR + m];
                    aF[i*4+1] = Ah[(kc+tig)*ASTR + m+8];
                    aF[i*4+2] = Ah[(kc+tig+4)*ASTR + m];
                    aF[i*4+3] = Ah[(kc+tig+4)*ASTR + m+8];
                }
                #pragma unroll
                for (int j=0;j<4;j++){
                    int n = wn*32 + j*8 + g;
                    bF[j*2+0] = Bh[(kc+tig)*ASTR + n];
                    bF[j*2+1] = Bh[(kc+tig+4)*ASTR + n];
                }
                #pragma unroll
                for (int i=0;i<4;i++)
                    #pragma unroll
                    for (int j=0;j<4;j++) mma_tf32(acc[i*4+j], &aF[i*4], &bF[j*2]);
                #pragma unroll
                for (int j=0;j<4;j++){
                    int n = wn*32 + j*8 + g;
                    bL2[j*2+0] = Bl[(kc+tig)*ASTR + n];
                    bL2[j*2+1] = Bl[(kc+tig+4)*ASTR + n];
                }
                #pragma unroll
                for (int i=0;i<4;i++)
                    #pragma unroll
                    for (int j=0;j<4;j++) mma_tf32(acc[i*4+j], &aF[i*4], &bL2[j*2]);
                #pragma unroll
                for (int i=0;i<4;i++){
                    int m = wm*64 + i*16 + g;
                    aF[i*4+0] = Al[(kc+tig)*ASTR + m];
                    aF[i*4+1] = Al[(kc+tig)*ASTR + m+8];
                    aF[i*4+2] = Al[(kc+tig+4)*ASTR + m];
                    aF[i*4+3] = Al[(kc+tig+4)*ASTR + m+8];
                }
                #pragma unroll
                for (int i=0;i<4;i++)
                    #pragma unroll
                    for (int j=0;j<4;j++) mma_tf32(acc[i*4+j], &aF[i*4], &bF[j*2]);
            }
        }
        if (t+1<nT){
            int nb=buf^1;
            #pragma unroll
            for (int i=0;i<2;i++){
                int kq=(akq+i*2)*4;
                float av[4]={ra[i].x,ra[i].y,ra[i].z,ra[i].w};
                #pragma unroll
                for (int c=0;c<4;c++){
                    unsigned hi,lo; tfsplit(av[c],hi,lo);
                    AH[nb*TB + (kq+c)*ASTR + arow] = hi;
                    AL[nb*TB + (kq+c)*ASTR + arow] = lo;
                }
                float bv[4]={rb[i].x,rb[i].y,rb[i].z,rb[i].w};
                int krow = bkk + i*8;
                #pragma unroll
                for (int c=0;c<4;c++){
                    unsigned hi,lo; tfsplit(bv[c],hi,lo);
                    BH[nb*TB + krow*ASTR + bn + c] = hi;
                    BL[nb*TB + krow*ASTR + bn + c] = lo;
                }
            }
        }
        __syncthreads();
        buf^=1;
    }

    #pragma unroll
    for (int i=0;i<4;i++){
        #pragma unroll
        for (int j=0;j<4;j++){
            const float* c = acc[i*4+j];
            int rowb = m0 + wm*64 + i*16 + g;
            int colb = n0 + wn*32 + j*8 + 2*tig;
            #pragma unroll
            for (int e=0;e<4;e++){
                int gm = rowb + (e>=2 ? 8 : 0);
                int gn = colb + (e&1);
                if (gn >= N) continue;
                float vv = c[e];
                if (epi==EPI_SILU)         vv = vv/(1.f+__expf(-vv));
                else if (epi==EPI_SIGMOID) vv = 1.f/(1.f+__expf(-vv));
                if (epi==EPI_HEAD) C[((gn>>6)*S + gm)*D + (gn&63)] = vv;
                else               C[(long)gm*N + gn] = vv;
            }
        }
    }
}

// ---------------- compression Phi ----------------
template<int P>
__device__ __forceinline__ void phi_level(const float* __restrict__ a,
                                          float* __restrict__ b,
                                          const float* __restrict__ W, int d)
{
    float accs[P];
    #pragma unroll
    for (int p=0;p<P;p++) accs[p]=0.f;
    #pragma unroll 4
    for (int j=0;j<128;j+=4){
        float w0=W[(j+0)*64+d], w1=W[(j+1)*64+d];
        float w2=W[(j+2)*64+d], w3=W[(j+3)*64+d];
        #pragma unroll
        for (int p=0;p<P;p++){
            float4 c = *(const float4*)&a[p*128+j];
            accs[p] += c.x*w0;
            accs[p] += c.y*w1;
            accs[p] += c.z*w2;
            accs[p] += c.w*w3;
        }
    }
    #pragma unroll
    for (int p=0;p<P;p++){
        float xx = accs[p];
        b[p*64+d] = xx / (1.f + __expf(-xx));
    }
}

__global__ __launch_bounds__(256)
void compress2(const float* __restrict__ ksrc, const float* __restrict__ vsrc,
               const float* __restrict__ pe_k, const float* __restrict__ down_k,
               const float* __restrict__ stop_k,
               const float* __restrict__ pe_v, const float* __restrict__ down_v,
               const float* __restrict__ stop_v,
               float* __restrict__ kc, float* __restrict__ vc)
{
    __shared__ __align__(16) float bufX[4*2048];
    __shared__ __align__(16) float bufY[4*1024];
    const int tid = threadIdx.x;
    const int d   = tid & 63;
    const int sub = tid >> 6;
    const int w   = blockIdx.x*4 + sub;
    const int h   = blockIdx.y;
    const int z   = blockIdx.z;
    const float* src  = z ? vsrc  : ksrc;
    const float* pe   = z ? pe_v  : pe_k;
    const float* down = z ? down_v: down_k;
    const float* stop = z ? stop_v: stop_k;
    float* dst        = z ? vc    : kc;

    float* X = bufX + sub*2048;
    float* Y = bufY + sub*1024;

    if (w > 0){
        int s0 = (w-1)*16;
        #pragma unroll
        for (int i=0;i<32;i++)
            X[i*64+d] = src[(h*S + s0+i)*D + d] + pe[i*64+d];
    }
    __syncthreads();

    phi_level<16>(X, Y, down,         d);  __syncthreads();
    phi_level<8> (Y, X, down + 8192,  d);  __syncthreads();
    phi_level<4> (X, Y, down + 16384, d);  __syncthreads();
    phi_level<2> (Y, X, down + 24576, d);  __syncthreads();
    phi_level<1> (X, Y, down + 32768, d);  __syncthreads();

    float a = 0.f;
    #pragma unroll
    for (int j=0;j<64;j+=4){
        float4 c = *(const float4*)&Y[j];
        a += c.x*stop[(j+0)*64+d];
        a += c.y*stop[(j+1)*64+d];
        a += c.z*stop[(j+2)*64+d];
        a += c.w*stop[(j+3)*64+d];
    }
    dst[(h*SCMP + w)*D + d] = (w > 0) ? a : 0.f;
}

// ---------------- compressed branch + conv + top-k selection ----------------
__global__ void cmp_attn(float scale)
{
    extern __shared__ float csm[];
    float* kc_s = csm;               // 128*65
    float* vc_s = kc_s + 128*65;     // 8192
    float* q_s  = vc_s + 8192;       // 64
    float* p_sm = q_s + 64;          // 128
    float* ps   = p_sm + 128;        // 32
    float* ps2  = ps + 32;           // 64
    float* red  = ps2 + 64;          // 4

    int h = blockIdx.y;
    int tid = threadIdx.x;
    int lane = tid & 31, wid = tid >> 5;

    for (int i=tid;i<8192;i+=128){
        kc_s[(i>>6)*65 + (i&63)] = d_kc[h*8192+i];
        vc_s[i] = d_vc[h*8192+i];
    }

    for (int qi=0;qi<8;qi++){
        int q = blockIdx.x*8 + qi;
        __syncthreads();
        if (tid < 64) q_s[tid] = d_q[(h*S + q)*D + tid];
        __syncthreads();

        int r = q >> 4;
        float sc = -INFINITY;
        {
            bool ok = (tid <= r-1) || (tid==0 && r<32);
            if (ok){
                float a=0.f;
                #pragma unroll
                for (int dd=0;dd<64;dd++) a += q_s[dd]*kc_s[tid*65+dd];
                sc = a*scale;
            }
        }
        float v = sc;
        #pragma unroll
        for (int off=16;off;off>>=1) v = fmaxf(v, __shfl_xor_sync(0xffffffffu,v,off));
        if (lane==0) red[wid]=v;
        __syncthreads();
        float m = fmaxf(fmaxf(red[0],red[1]),fmaxf(red[2],red[3]));
        float p = __expf(sc - m);
        p_sm[tid] = p;
        __syncthreads();
        float sv = p;
        #pragma unroll
        for (int off=16;off;off>>=1) sv += __shfl_xor_sync(0xffffffffu,sv,off);
        if (lane==0) red[wid]=sv;
        __syncthreads();
        float l = red[0]+red[1]+red[2]+red[3];

        if (wid == 3){
            int n = lane;
            float a = 2.f*(p_sm[4*n] + p_sm[4*n+1] + p_sm[4*n+2]) + p_sm[4*n+3];
            if (4*n-1 >= 0) a += p_sm[4*n-1];
            ps[n] = a;
            __syncwarp();
            float mv = ps[n];
            int cnt = 0;
            #pragma unroll
            for (int i2=0;i2<32;i2++){
                float vi = ps[i2];
                cnt += (vi > mv) || (vi == mv && i2 < n);
            }
            bool sel = (cnt < 16) && (n < (q >> 6));
            unsigned msk = __ballot_sync(0xffffffffu, sel);
            if (lane==0) d_bm[h*S + q] = msk;
        }
        float a;
        if (tid < 64){
            a = 0.f;
            for (int j=0;j<64;j++) a += p_sm[j]*vc_s[j*64+tid];
        } else {
            float b = 0.f;
            int dd = tid - 64;
            for (int j=64;j<128;j++) b += p_sm[j]*vc_s[j*64+dd];
            ps2[dd] = b;
            a = 0.f;
        }
        __syncthreads();
        if (tid < 64){
            float g0 = d_gate[q*GDIM + h*3 + 0];
            d_o1[q*DIMM + h*64 + tid] = g0 * ((a + ps2[tid]) / l);
        }
    }
}

// ---------------- tensor-core flash attention (tf32x3) ----------------
// MODE 0 = selection (d_o2), MODE 1 = sliding window (d_o3)
// 256 thr = 8 warps: band=wid&3 (16 query rows), half=wid>>2 (32 keys/dims).
template<int MODE>
__global__ __launch_bounds__(256) void attn_flash(float scale)
{
    extern __shared__ float fsm[];
    float* q_s   = fsm;             // [64][PS]
    float* k_s   = q_s + 64*PS;     // [key][d]
    float* v_s   = k_s + 64*PS;     // [key][d]
    float* p_s   = v_s + 64*PS;     // [row][key]
    float* m_s   = p_s + 64*PS;     // 64
    float* l_s   = m_s + 64;        // 64
    float* redmx = l_s + 64;        // [2][64]
    float* redsm = redmx + 128;     // [2][64]
    unsigned* msk_s = (unsigned*)(redsm + 128);  // 64
    unsigned* u_s   = msk_s + 64;                // 1

    const int tq = blockIdx.x, h = blockIdx.y;
    const int q0 = tq*64;
    const int tid = threadIdx.x;
    const int wid = tid >> 5, lane = tid & 31;
    const int g = lane >> 2, tig = lane & 3;
    const int band = wid & 3, hn = wid >> 2;
    const int r0 = band*16 + g;
    const int r1 = r0 + 8;

    #pragma unroll
    for (int r2=0;r2<4;r2++){
        int li = tid + r2*256;
        int row = li >> 4, c4 = (li & 15)*4;
        *(float4*)&q_s[row*PS + c4] = *(const float4*)&d_q[(h*S + q0+row)*D + c4];
    }
    if (tid < 64){
        m_s[tid] = -INFINITY; l_s[tid] = 0.f;
        if (MODE==0) msk_s[tid] = d_bm[h*S + q0 + tid];
    }
    __syncthreads();

    unsigned uni = 0xFFFFFFFFu;
    if (MODE==0){
        if (tid==0){
            unsigned u=0;
            for (int i=0;i<64;i++) u |= msk_s[i];
            u_s[0]=u;
        }
        __syncthreads();
        uni = u_s[0];
    }

    int nlo, nhi;
    if (MODE==0){ nlo=0; nhi=(uni==0u)?0:tq; }
    else { nlo = tq-8; if (nlo<0) nlo=0; nhi = tq+1; }

    float acc[4][4];
    #pragma unroll
    for (int j=0;j<4;j++)
        #pragma unroll
        for (int e=0;e<4;e++) acc[j][e]=0.f;

    for (int n=nlo;n<nhi;n++){
        if (MODE==0 && !((uni>>n)&1u)) continue;

        #pragma unroll
        for (int r2=0;r2<4;r2++){
            int li = tid + r2*256;
            int row = li >> 4, c4 = (li & 15)*4;
            *(float4*)&k_s[row*PS + c4] = *(const float4*)&d_k[(h*S + n*64+row)*D + c4];
            *(float4*)&v_s[row*PS + c4] = *(const float4*)&d_v[(h*S + n*64+row)*D + c4];
        }
        __syncthreads();

        // ---- S = Q K^T for this warp's 16x32 patch ----
        float sc4[4][4];
        #pragma unroll
        for (int j=0;j<4;j++)
            #pragma unroll
            for (int e=0;e<4;e++) sc4[j][e]=0.f;

        #pragma unroll
        for (int kc=0;kc<64;kc+=8){
            unsigned ah[4], al[4];
            tfsplit(q_s[r0*PS + kc + tig],     ah[0], al[0]);
            tfsplit(q_s[r1*PS + kc + tig],     ah[1], al[1]);
            tfsplit(q_s[r0*PS + kc + tig + 4], ah[2], al[2]);
            tfsplit(q_s[r1*PS + kc + tig + 4], ah[3], al[3]);
            #pragma unroll
            for (int j=0;j<4;j++){
                int nb = hn*32 + j*8 + g;
                unsigned bh[2], bl[2];
                tfsplit(k_s[nb*PS + kc + tig],     bh[0], bl[0]);
                tfsplit(k_s[nb*PS + kc + tig + 4], bh[1], bl[1]);
                mma_tf32(sc4[j], ah, bh);
                mma_tf32(sc4[j], ah, bl);
                mma_tf32(sc4[j], al, bh);
            }
        }

        // ---- mask + scale + row max ----
        float mx0 = -INFINITY, mx1 = -INFINITY;
        bool okr0 = true, okr1 = true;
        if (MODE==0){ okr0 = (msk_s[r0]>>n)&1u; okr1 = (msk_s[r1]>>n)&1u; }
        #pragma unroll
        for (int j=0;j<4;j++){
            #pragma unroll
            for (int e=0;e<4;e++){
                int row = (e>=2)? r1 : r0;
                int qg  = q0 + row;
                int t   = n*64 + hn*32 + j*8 + 2*tig + (e&1);
                bool ok;
                if (MODE==0) ok = (e>=2)? okr1 : okr0;
                else ok = (t <= qg) && (qg - t <= 512);
                float val = ok ? sc4[j][e]*scale : -INFINITY;
                sc4[j][e] = val;
                if (e<2) mx0 = fmaxf(mx0, val); else mx1 = fmaxf(mx1, val);
            }
        }
        #pragma unroll
        for (int off=1;off<4;off<<=1){
            mx0 = fmaxf(mx0, __shfl_xor_sync(0xffffffffu, mx0, off));
            mx1 = fmaxf(mx1, __shfl_xor_sync(0xffffffffu, mx1, off));
        }
        if (tig==0){ redmx[hn*64 + r0] = mx0; redmx[hn*64 + r1] = mx1; }
        __syncthreads();

        float mo0 = m_s[r0], mo1 = m_s[r1];
        float mn0 = fmaxf(mo0, fmaxf(redmx[r0], redmx[64+r0]));
        float mn1 = fmaxf(mo1, fmaxf(redmx[r1], redmx[64+r1]));
        float al0 = 1.f, al1 = 1.f;
        float sm0 = 0.f, sm1 = 0.f;
        if (mn0 != -INFINITY) al0 = __expf(mo0 - mn0);
        if (mn1 != -INFINITY) al1 = __expf(mo1 - mn1);
        #pragma unroll
        for (int j=0;j<4;j++){
            #pragma unroll
            for (int e=0;e<4;e++){
                float mn = (e>=2)? mn1 : mn0;
                float p = (mn == -INFINITY) ? 0.f : __expf(sc4[j][e] - mn);
                sc4[j][e] = p;
                if (e<2) sm0 += p; else sm1 += p;
            }
        }
        #pragma unroll
        for (int off=1;off<4;off<<=1){
            sm0 += __shfl_xor_sync(0xffffffffu, sm0, off);
            sm1 += __shfl_xor_sync(0xffffffffu, sm1, off);
        }
        if (tig==0){ redsm[hn*64 + r0] = sm0; redsm[hn*64 + r1] = sm1; }
        // write P to smem
        #pragma unroll
        for (int j=0;j<4;j++){
            int cb = hn*32 + j*8 + 2*tig;
            p_s[r0*PS + cb]   = sc4[j][0];
            p_s[r0*PS + cb+1] = sc4[j][1];
            p_s[r1*PS + cb]   = sc4[j][2];
            p_s[r1*PS + cb+1] = sc4[j][3];
        }
        // rescale accumulators
        #pragma unroll
        for (int j=0;j<4;j++){
            acc[j][0]*=al0; acc[j][1]*=al0; acc[j][2]*=al1; acc[j][3]*=al1;
        }
        __syncthreads();
        if (hn==0 && tig==0){
            m_s[r0] = mn0; l_s[r0] = l_s[r0]*al0 + redsm[r0] + redsm[64+r0];
            m_s[r1] = mn1; l_s[r1] = l_s[r1]*al1 + redsm[r1] + redsm[64+r1];
        }

        // ---- O += P V ----
        #pragma unroll
        for (int kc=0;kc<64;kc+=8){
            unsigned ah[4], al2[4];
            tfsplit(p_s[r0*PS + kc + tig],     ah[0], al2[0]);
            tfsplit(p_s[r1*PS + kc + tig],     ah[1], al2[1]);
            tfsplit(p_s[r0*PS + kc + tig + 4], ah[2], al2[2]);
            tfsplit(p_s[r1*PS + kc + tig + 4], ah[3], al2[3]);
            #pragma unroll
            for (int j=0;j<4;j++){
                int nb = hn*32 + j*8 + g;
                unsigned bh[2], bl[2];
                tfsplit(v_s[(kc+tig)*PS + nb],     bh[0], bl[0]);
                tfsplit(v_s[(kc+tig+4)*PS + nb],   bh[1], bl[1]);
                mma_tf32(acc[j], ah, bh);
                mma_tf32(acc[j], ah, bl);
                mma_tf32(acc[j], al2, bh);
            }
        }
        __syncthreads();
    }

    // ---- epilogue ----
    float l0 = l_s[r0], l1 = l_s[r1];
    float in0 = (l0 > 0.f) ? 1.f/l0 : 0.f;
    float in1 = (l1 > 0.f) ? 1.f/l1 : 0.f;
    const int gi = (MODE==0) ? 1 : 2;
    float g0 = d_gate[(q0+r0)*GDIM + h*3 + gi];
    float g1 = d_gate[(q0+r1)*GDIM + h*3 + gi];
    float* outp = (MODE==0) ? d_o2 : d_o3;
    #pragma unroll
    for (int j=0;j<4;j++){
        int cb = hn*32 + j*8 + 2*tig;
        outp[(q0+r0)*DIMM + h*64 + cb]   = g0*acc[j][0]*in0;
        outp[(q0+r0)*DIMM + h*64 + cb+1] = g0*acc[j][1]*in0;
        outp[(q0+r1)*DIMM + h*64 + cb]   = g1*acc[j][2]*in1;
        outp[(q0+r1)*DIMM + h*64 + cb+1] = g1*acc[j][3]*in1;
    }
}

// ---------------- launch ----------------
static cudaStream_t sA = nullptr, sB = nullptr;
static cudaEvent_t e0, e_qkv, e_gate, e_cmp, e_f0, e_f1;

extern "C" void kernel_launch(void* const* d_in, const int* in_sizes, int n_in,
                              void* d_out, int out_size)
{
    (void)in_sizes; (void)n_in; (void)out_size;
    const float* x      = (const float*)d_in[0];
    const float* wq     = (const float*)d_in[1];
    const float* wk     = (const float*)d_in[2];
    const float* wv     = (const float*)d_in[3];
    const float* wo     = (const float*)d_in[4];
    const float* gw1    = (const float*)d_in[5];
    const float* gw2    = (const float*)d_in[6];
    const float* pe_k   = (const float*)d_in[7];
    const float* down_k = (const float*)d_in[8];
    const float* stop_k = (const float*)d_in[9];
    const float* pe_v   = (const float*)d_in[10];
    const float* down_v = (const float*)d_in[11];
    const float* stop_v = (const float*)d_in[12];

    const int GSM = 4*2*BK*ASTR*4;
    const int CSM = (128*65 + 8192 + 64+128+32+64+4)*4;
    const int FSM = (4*64*PS + 64 + 64 + 128 + 128)*4 + (64+1)*4 + 16;

    if (!sA){
        cudaStreamCreateWithFlags(&sA, cudaStreamNonBlocking);
        cudaStreamCreateWithFlags(&sB, cudaStreamNonBlocking);
        cudaEventCreateWithFlags(&e0,     cudaEventDisableTiming);
        cudaEventCreateWithFlags(&e_qkv,  cudaEventDisableTiming);
        cudaEventCreateWithFlags(&e_gate, cudaEventDisableTiming);
        cudaEventCreateWithFlags(&e_cmp,  cudaEventDisableTiming);
        cudaEventCreateWithFlags(&e_f0,   cudaEventDisableTiming);
        cudaEventCreateWithFlags(&e_f1,   cudaEventDisableTiming);
        cudaFuncSetAttribute(gemm_tc,  cudaFuncAttributeMaxDynamicSharedMemorySize, GSM);
        cudaFuncSetAttribute(cmp_attn, cudaFuncAttributeMaxDynamicSharedMemorySize, CSM);
        cudaFuncSetAttribute(attn_flash<0>, cudaFuncAttributeMaxDynamicSharedMemorySize, FSM);
        cudaFuncSetAttribute(attn_flash<1>, cudaFuncAttributeMaxDynamicSharedMemorySize, FSM);
    }

    float *q_p, *k_p, *v_p, *g1_p, *gate_p, *kc_p, *vc_p, *o1_p, *o2_p, *o3_p;
    cudaGetSymbolAddress((void**)&q_p,    d_q);
    cudaGetSymbolAddress((void**)&k_p,    d_k);
    cudaGetSymbolAddress((void**)&v_p,    d_v);
    cudaGetSymbolAddress((void**)&g1_p,   d_g1);
    cudaGetSymbolAddress((void**)&gate_p, d_gate);
    cudaGetSymbolAddress((void**)&kc_p,   d_kc);
    cudaGetSymbolAddress((void**)&vc_p,   d_vc);
    cudaGetSymbolAddress((void**)&o1_p,   d_o1);
    cudaGetSymbolAddress((void**)&o2_p,   d_o2);
    cudaGetSymbolAddress((void**)&o3_p,   d_o3);

    const float scale = 0.125f;

    cudaEventRecord(e0, 0);
    cudaStreamWaitEvent(sA, e0, 0);

    // stream0: fused QKV projection
    gemm_tc<<<dim3(8,16,3),256,GSM>>>(x, nullptr, nullptr, wq, wk, wv,
                                      q_p, k_p, v_p, S, 1024, DIMM, EPI_HEAD);
    cudaEventRecord(e_qkv, 0);

    // sA: gate chain
    gemm_tc<<<dim3(4,16,1),256,GSM,sA>>>(x, nullptr, nullptr, gw1, gw1, gw1,
                                         g1_p, g1_p, g1_p, S, 512, DIMM, EPI_SILU);
    gemm_tc<<<dim3(1,16,1),256,GSM,sA>>>(g1_p, nullptr, nullptr, gw2, gw2, gw2,
                                         gate_p, gate_p, gate_p, S, GDIM, 512, EPI_SIGMOID);
    cudaEventRecord(e_gate, sA);

    // stream0: compression, compressed branch (+ masks)
    compress2<<<dim3(32,16,2),256>>>(k_p, v_p, pe_k, down_k, stop_k,
                                     pe_v, down_v, stop_v, kc_p, vc_p);
    cudaStreamWaitEvent(0, e_gate, 0);
    cmp_attn<<<dim3(S/8,16),128,CSM>>>(scale);
    cudaEventRecord(e_cmp, 0);

    // sA: sliding-window branch
    cudaStreamWaitEvent(sA, e_qkv, 0);
    attn_flash<1><<<dim3(S/64,16),256,FSM,sA>>>(scale);
    cudaEventRecord(e_f1, sA);

    // sB: selection branch
    cudaStreamWaitEvent(sB, e_cmp, 0);
    cudaStreamWaitEvent(sB, e_gate, 0);
    attn_flash<0><<<dim3(S/64,16),256,FSM,sB>>>(scale);
    cudaEventRecord(e_f0, sB);

    // join + output projection
    cudaStreamWaitEvent(0, e_f1, 0);
    cudaStreamWaitEvent(0, e_f0, 0);
    gemm_tc<<<dim3(8,16,1),256,GSM>>>(o1_p, o2_p, o3_p, wo, wo, wo,
                                      (float*)d_out, (float*)d_out, (float*)d_out,
                                      S, DIMM, DIMM, EPI_NONE);
}

// round 9
// speedup vs baseline: 1.2957x; 1.0016x over previous
#include <cuda_runtime.h>
#include <math.h>

#define H    16
#define S    2048
#define D    64
#define DIMM 1024
#define SCMP 128
#define GDIM 48

#define BK 16
#define ASTR 132   // smem row stride (words) for GEMM tiles
#define PS   68    // smem row stride (floats) for flash planes

// ---------------- scratch ----------------
__device__ float d_q[H*S*D];
__device__ float d_k[H*S*D];
__device__ float d_v[H*S*D];
__device__ float d_g1[S*512];
__device__ float d_gate[S*GDIM];
__device__ float d_kc[H*SCMP*D];
__device__ float d_vc[H*SCMP*D];
__device__ float d_o1[S*DIMM];
__device__ float d_o2[S*DIMM];
__device__ float d_o3[S*DIMM];
__device__ unsigned d_bm[H*S];

enum { EPI_NONE=0, EPI_SILU=1, EPI_SIGMOID=2, EPI_HEAD=3 };

__device__ __forceinline__ unsigned f2tf(float x){
    unsigned r; asm("cvt.rna.tf32.f32 %0, %1;" : "=r"(r) : "f"(x)); return r;
}
__device__ __forceinline__ void mma_tf32(float* c, const unsigned* a, const unsigned* b){
    asm volatile("mma.sync.aligned.m16n8k8.row.col.f32.tf32.tf32.f32 "
        "{%0,%1,%2,%3}, {%4,%5,%6,%7}, {%8,%9}, {%0,%1,%2,%3};"
        : "+f"(c[0]),"+f"(c[1]),"+f"(c[2]),"+f"(c[3])
        : "r"(a[0]),"r"(a[1]),"r"(a[2]),"r"(a[3]), "r"(b[0]),"r"(b[1]));
}
// split fp32 -> (hi,lo) tf32 pair
__device__ __forceinline__ void tfsplit(float x, unsigned& hi, unsigned& lo){
    hi = f2tf(x);
    lo = f2tf(x - __uint_as_float(hi));
}

// ---------------- tf32x3 tensor-core GEMM ----------------
__global__ __launch_bounds__(256)
void gemm_tc(const float* __restrict__ A,
             const float* __restrict__ Ab,
             const float* __restrict__ Ac,
             const float* __restrict__ B0,
             const float* __restrict__ B1,
             const float* __restrict__ B2,
             float* __restrict__ C0,
             float* __restrict__ C1,
             float* __restrict__ C2,
             int M, int N, int K, int epi)
{
    extern __shared__ unsigned gsm[];
    const int TB = BK*ASTR;
    unsigned* AH = gsm;
    unsigned* AL = AH + 2*TB;
    unsigned* BH = AL + 2*TB;
    unsigned* BL = BH + 2*TB;

    const int tid = threadIdx.x;
    const int wid = tid >> 5, lane = tid & 31;
    const int wm = wid >> 2, wn = wid & 3;
    const int g = lane >> 2, tig = lane & 3;
    const int m0 = blockIdx.y*128, n0 = blockIdx.x*128;
    const float* B = blockIdx.z==0 ? B0 : (blockIdx.z==1 ? B1 : B2);
    float* C = blockIdx.z==0 ? C0 : (blockIdx.z==1 ? C1 : C2);

    const int arow = tid & 127;
    const int akq  = tid >> 7;
    const int bkk  = tid >> 5;
    const int bn   = (tid & 31)*4;
    const long abase = (long)(m0 + arow)*K;
    const bool bok = (n0 + bn) < N;

    float acc[16][4];
    #pragma unroll
    for (int i=0;i<16;i++){ acc[i][0]=0.f; acc[i][1]=0.f; acc[i][2]=0.f; acc[i][3]=0.f; }

    const int nT = K/BK;
    float4 ra[2], rb[2];

    #pragma unroll
    for (int i=0;i<2;i++){
        long off = abase + (akq + i*2)*4;
        float4 v = *(const float4*)(A + off);
        if (Ab){
            float4 w = *(const float4*)(Ab + off);
            float4 u = *(const float4*)(Ac + off);
            v.x+=w.x+u.x; v.y+=w.y+u.y; v.z+=w.z+u.z; v.w+=w.w+u.w;
        }
        ra[i]=v;
        rb[i]= bok ? *(const float4*)(B + (long)(bkk + i*8)*N + n0 + bn)
                   : make_float4(0.f,0.f,0.f,0.f);
    }
    #pragma unroll
    for (int i=0;i<2;i++){
        int kq=(akq+i*2)*4;
        float av[4]={ra[i].x,ra[i].y,ra[i].z,ra[i].w};
        #pragma unroll
        for (int c=0;c<4;c++){
            unsigned hi,lo; tfsplit(av[c],hi,lo);
            AH[(kq+c)*ASTR + arow] = hi;
            AL[(kq+c)*ASTR + arow] = lo;
        }
        float bv[4]={rb[i].x,rb[i].y,rb[i].z,rb[i].w};
        int krow = bkk + i*8;
        #pragma unroll
        for (int c=0;c<4;c++){
            unsigned hi,lo; tfsplit(bv[c],hi,lo);
            BH[krow*ASTR + bn + c] = hi;
            BL[krow*ASTR + bn + c] = lo;
        }
    }
    __syncthreads();

    int buf=0;
    for (int t=0;t<nT;t++){
        if (t+1<nT){
            int k0=(t+1)*BK;
            #pragma unroll
            for (int i=0;i<2;i++){
                long off = abase + k0 + (akq + i*2)*4;
                float4 v = *(const float4*)(A + off);
                if (Ab){
                    float4 w = *(const float4*)(Ab + off);
                    float4 u = *(const float4*)(Ac + off);
                    v.x+=w.x+u.x; v.y+=w.y+u.y; v.z+=w.z+u.z; v.w+=w.w+u.w;
                }
                ra[i]=v;
                rb[i]= bok ? *(const float4*)(B + (long)(k0 + bkk + i*8)*N + n0 + bn)
                           : make_float4(0.f,0.f,0.f,0.f);
            }
        }
        {
            const unsigned* Ah = AH + buf*TB;
            const unsigned* Al = AL + buf*TB;
            const unsigned* Bh = BH + buf*TB;
            const unsigned* Bl = BL + buf*TB;
            #pragma unroll
            for (int kc=0;kc<BK;kc+=8){
                unsigned aF[16], bF[8], bL2[8];
                #pragma unroll
                for (int i=0;i<4;i++){
                    int m = wm*64 + i*16 + g;
                    aF[i*4+0] = Ah[(kc+tig)*ASTR + m];
                    aF[i*4+1] = Ah[(kc+tig)*ASTR + m+8];
                    aF[i*4+2] = Ah[(kc+tig+4)*ASTR + m];
                    aF[i*4+3] = Ah[(kc+tig+4)*ASTR + m+8];
                }
                #pragma unroll
                for (int j=0;j<4;j++){
                    int n = wn*32 + j*8 + g;
                    bF[j*2+0] = Bh[(kc+tig)*ASTR + n];
                    bF[j*2+1] = Bh[(kc+tig+4)*ASTR + n];
                }
                #pragma unroll
                for (int i=0;i<4;i++)
                    #pragma unroll
                    for (int j=0;j<4;j++) mma_tf32(acc[i*4+j], &aF[i*4], &bF[j*2]);
                #pragma unroll
                for (int j=0;j<4;j++){
                    int n = wn*32 + j*8 + g;
                    bL2[j*2+0] = Bl[(kc+tig)*ASTR + n];
                    bL2[j*2+1] = Bl[(kc+tig+4)*ASTR + n];
                }
                #pragma unroll
                for (int i=0;i<4;i++)
                    #pragma unroll
                    for (int j=0;j<4;j++) mma_tf32(acc[i*4+j], &aF[i*4], &bL2[j*2]);
                #pragma unroll
                for (int i=0;i<4;i++){
                    int m = wm*64 + i*16 + g;
                    aF[i*4+0] = Al[(kc+tig)*ASTR + m];
                    aF[i*4+1] = Al[(kc+tig)*ASTR + m+8];
                    aF[i*4+2] = Al[(kc+tig+4)*ASTR + m];
                    aF[i*4+3] = Al[(kc+tig+4)*ASTR + m+8];
                }
                #pragma unroll
                for (int i=0;i<4;i++)
                    #pragma unroll
                    for (int j=0;j<4;j++) mma_tf32(acc[i*4+j], &aF[i*4], &bF[j*2]);
            }
        }
        if (t+1<nT){
            int nb=buf^1;
            #pragma unroll
            for (int i=0;i<2;i++){
                int kq=(akq+i*2)*4;
                float av[4]={ra[i].x,ra[i].y,ra[i].z,ra[i].w};
                #pragma unroll
                for (int c=0;c<4;c++){
                    unsigned hi,lo; tfsplit(av[c],hi,lo);
                    AH[nb*TB + (kq+c)*ASTR + arow] = hi;
                    AL[nb*TB + (kq+c)*ASTR + arow] = lo;
                }
                float bv[4]={rb[i].x,rb[i].y,rb[i].z,rb[i].w};
                int krow = bkk + i*8;
                #pragma unroll
                for (int c=0;c<4;c++){
                    unsigned hi,lo; tfsplit(bv[c],hi,lo);
                    BH[nb*TB + krow*ASTR + bn + c] = hi;
                    BL[nb*TB + krow*ASTR + bn + c] = lo;
                }
            }
        }
        __syncthreads();
        buf^=1;
    }

    #pragma unroll
    for (int i=0;i<4;i++){
        #pragma unroll
        for (int j=0;j<4;j++){
            const float* c = acc[i*4+j];
            int rowb = m0 + wm*64 + i*16 + g;
            int colb = n0 + wn*32 + j*8 + 2*tig;
            #pragma unroll
            for (int e=0;e<4;e++){
                int gm = rowb + (e>=2 ? 8 : 0);
                int gn = colb + (e&1);
                if (gn >= N) continue;
                float vv = c[e];
                if (epi==EPI_SILU)         vv = vv/(1.f+__expf(-vv));
                else if (epi==EPI_SIGMOID) vv = 1.f/(1.f+__expf(-vv));
                if (epi==EPI_HEAD) C[((gn>>6)*S + gm)*D + (gn&63)] = vv;
                else               C[(long)gm*N + gn] = vv;
            }
        }
    }
}

// ---------------- compression Phi ----------------
template<int P>
__device__ __forceinline__ void phi_level(const float* __restrict__ a,
                                          float* __restrict__ b,
                                          const float* __restrict__ W, int d)
{
    float accs[P];
    #pragma unroll
    for (int p=0;p<P;p++) accs[p]=0.f;
    #pragma unroll 4
    for (int j=0;j<128;j+=4){
        float w0=W[(j+0)*64+d], w1=W[(j+1)*64+d];
        float w2=W[(j+2)*64+d], w3=W[(j+3)*64+d];
        #pragma unroll
        for (int p=0;p<P;p++){
            float4 c = *(const float4*)&a[p*128+j];
            accs[p] += c.x*w0;
            accs[p] += c.y*w1;
            accs[p] += c.z*w2;
            accs[p] += c.w*w3;
        }
    }
    #pragma unroll
    for (int p=0;p<P;p++){
        float xx = accs[p];
        b[p*64+d] = xx / (1.f + __expf(-xx));
    }
}

__global__ __launch_bounds__(256)
void compress2(const float* __restrict__ ksrc, const float* __restrict__ vsrc,
               const float* __restrict__ pe_k, const float* __restrict__ down_k,
               const float* __restrict__ stop_k,
               const float* __restrict__ pe_v, const float* __restrict__ down_v,
               const float* __restrict__ stop_v,
               float* __restrict__ kc, float* __restrict__ vc)
{
    __shared__ __align__(16) float bufX[4*2048];
    __shared__ __align__(16) float bufY[4*1024];
    const int tid = threadIdx.x;
    const int d   = tid & 63;
    const int sub = tid >> 6;
    const int w   = blockIdx.x*4 + sub;
    const int h   = blockIdx.y;
    const int z   = blockIdx.z;
    const float* src  = z ? vsrc  : ksrc;
    const float* pe   = z ? pe_v  : pe_k;
    const float* down = z ? down_v: down_k;
    const float* stop = z ? stop_v: stop_k;
    float* dst        = z ? vc    : kc;

    float* X = bufX + sub*2048;
    float* Y = bufY + sub*1024;

    if (w > 0){
        int s0 = (w-1)*16;
        #pragma unroll
        for (int i=0;i<32;i++)
            X[i*64+d] = src[(h*S + s0+i)*D + d] + pe[i*64+d];
    }
    __syncthreads();

    phi_level<16>(X, Y, down,         d);  __syncthreads();
    phi_level<8> (Y, X, down + 8192,  d);  __syncthreads();
    phi_level<4> (X, Y, down + 16384, d);  __syncthreads();
    phi_level<2> (Y, X, down + 24576, d);  __syncthreads();
    phi_level<1> (X, Y, down + 32768, d);  __syncthreads();

    float a = 0.f;
    #pragma unroll
    for (int j=0;j<64;j+=4){
        float4 c = *(const float4*)&Y[j];
        a += c.x*stop[(j+0)*64+d];
        a += c.y*stop[(j+1)*64+d];
        a += c.z*stop[(j+2)*64+d];
        a += c.w*stop[(j+3)*64+d];
    }
    dst[(h*SCMP + w)*D + d] = (w > 0) ? a : 0.f;
}

// ---------------- compressed branch + conv + top-k selection ----------------
__global__ void cmp_attn(float scale)
{
    extern __shared__ float csm[];
    float* kc_s = csm;               // 128*65
    float* vc_s = kc_s + 128*65;     // 8192
    float* q_s  = vc_s + 8192;       // 64
    float* p_sm = q_s + 64;          // 128
    float* ps   = p_sm + 128;        // 32
    float* ps2  = ps + 32;           // 64
    float* red  = ps2 + 64;          // 4

    int h = blockIdx.y;
    int tid = threadIdx.x;
    int lane = tid & 31, wid = tid >> 5;

    for (int i=tid;i<8192;i+=128){
        kc_s[(i>>6)*65 + (i&63)] = d_kc[h*8192+i];
        vc_s[i] = d_vc[h*8192+i];
    }

    for (int qi=0;qi<8;qi++){
        int q = blockIdx.x*8 + qi;
        __syncthreads();
        if (tid < 64) q_s[tid] = d_q[(h*S + q)*D + tid];
        __syncthreads();

        int r = q >> 4;
        float sc = -INFINITY;
        {
            bool ok = (tid <= r-1) || (tid==0 && r<32);
            if (ok){
                float a=0.f;
                #pragma unroll
                for (int dd=0;dd<64;dd++) a += q_s[dd]*kc_s[tid*65+dd];
                sc = a*scale;
            }
        }
        float v = sc;
        #pragma unroll
        for (int off=16;off;off>>=1) v = fmaxf(v, __shfl_xor_sync(0xffffffffu,v,off));
        if (lane==0) red[wid]=v;
        __syncthreads();
        float m = fmaxf(fmaxf(red[0],red[1]),fmaxf(red[2],red[3]));
        float p = __expf(sc - m);
        p_sm[tid] = p;
        __syncthreads();
        float sv = p;
        #pragma unroll
        for (int off=16;off;off>>=1) sv += __shfl_xor_sync(0xffffffffu,sv,off);
        if (lane==0) red[wid]=sv;
        __syncthreads();
        float l = red[0]+red[1]+red[2]+red[3];

        if (wid == 3){
            int n = lane;
            float a = 2.f*(p_sm[4*n] + p_sm[4*n+1] + p_sm[4*n+2]) + p_sm[4*n+3];
            if (4*n-1 >= 0) a += p_sm[4*n-1];
            ps[n] = a;
            __syncwarp();
            float mv = ps[n];
            int cnt = 0;
            #pragma unroll
            for (int i2=0;i2<32;i2++){
                float vi = ps[i2];
                cnt += (vi > mv) || (vi == mv && i2 < n);
            }
            bool sel = (cnt < 16) && (n < (q >> 6));
            unsigned msk = __ballot_sync(0xffffffffu, sel);
            if (lane==0) d_bm[h*S + q] = msk;
        }
        float a;
        if (tid < 64){
            a = 0.f;
            for (int j=0;j<64;j++) a += p_sm[j]*vc_s[j*64+tid];
        } else {
            float b = 0.f;
            int dd = tid - 64;
            for (int j=64;j<128;j++) b += p_sm[j]*vc_s[j*64+dd];
            ps2[dd] = b;
            a = 0.f;
        }
        __syncthreads();
        if (tid < 64){
            float g0 = d_gate[q*GDIM + h*3 + 0];
            d_o1[q*DIMM + h*64 + tid] = g0 * ((a + ps2[tid]) / l);
        }
    }
}

// ---------------- tensor-core flash attention (tf32x3) ----------------
// MODE 0 = selection (d_o2), MODE 1 = sliding window (d_o3)
// 256 thr = 8 warps: band=wid&3 (16 query rows), half=wid>>2 (32 keys/dims).
template<int MODE>
__global__ __launch_bounds__(256) void attn_flash(float scale)
{
    extern __shared__ float fsm[];
    float* q_s   = fsm;             // [64][PS]
    float* k_s   = q_s + 64*PS;     // [key][d]
    float* v_s   = k_s + 64*PS;     // [key][d]
    float* p_s   = v_s + 64*PS;     // [row][key]
    float* m_s   = p_s + 64*PS;     // 64
    float* l_s   = m_s + 64;        // 64
    float* redmx = l_s + 64;        // [2][64]
    float* redsm = redmx + 128;     // [2][64]
    unsigned* msk_s = (unsigned*)(redsm + 128);  // 64
    unsigned* u_s   = msk_s + 64;                // 1

    const int tq = blockIdx.x, h = blockIdx.y;
    const int q0 = tq*64;
    const int tid = threadIdx.x;
    const int wid = tid >> 5, lane = tid & 31;
    const int g = lane >> 2, tig = lane & 3;
    const int band = wid & 3, hn = wid >> 2;
    const int r0 = band*16 + g;
    const int r1 = r0 + 8;

    #pragma unroll
    for (int r2=0;r2<4;r2++){
        int li = tid + r2*256;
        int row = li >> 4, c4 = (li & 15)*4;
        *(float4*)&q_s[row*PS + c4] = *(const float4*)&d_q[(h*S + q0+row)*D + c4];
    }
    if (tid < 64){
        m_s[tid] = -INFINITY; l_s[tid] = 0.f;
        if (MODE==0) msk_s[tid] = d_bm[h*S + q0 + tid];
    }
    __syncthreads();

    unsigned uni = 0xFFFFFFFFu;
    if (MODE==0){
        if (tid==0){
            unsigned u=0;
            for (int i=0;i<64;i++) u |= msk_s[i];
            u_s[0]=u;
        }
        __syncthreads();
        uni = u_s[0];
    }

    int nlo, nhi;
    if (MODE==0){ nlo=0; nhi=(uni==0u)?0:tq; }
    else { nlo = tq-8; if (nlo<0) nlo=0; nhi = tq+1; }

    float acc[4][4];
    #pragma unroll
    for (int j=0;j<4;j++)
        #pragma unroll
        for (int e=0;e<4;e++) acc[j][e]=0.f;

    for (int n=nlo;n<nhi;n++){
        if (MODE==0 && !((uni>>n)&1u)) continue;

        #pragma unroll
        for (int r2=0;r2<4;r2++){
            int li = tid + r2*256;
            int row = li >> 4, c4 = (li & 15)*4;
            *(float4*)&k_s[row*PS + c4] = *(const float4*)&d_k[(h*S + n*64+row)*D + c4];
            *(float4*)&v_s[row*PS + c4] = *(const float4*)&d_v[(h*S + n*64+row)*D + c4];
        }
        __syncthreads();

        // ---- S = Q K^T for this warp's 16x32 patch ----
        float sc4[4][4];
        #pragma unroll
        for (int j=0;j<4;j++)
            #pragma unroll
            for (int e=0;e<4;e++) sc4[j][e]=0.f;

        #pragma unroll
        for (int kc=0;kc<64;kc+=8){
            unsigned ah[4], al[4];
            tfsplit(q_s[r0*PS + kc + tig],     ah[0], al[0]);
            tfsplit(q_s[r1*PS + kc + tig],     ah[1], al[1]);
            tfsplit(q_s[r0*PS + kc + tig + 4], ah[2], al[2]);
            tfsplit(q_s[r1*PS + kc + tig + 4], ah[3], al[3]);
            #pragma unroll
            for (int j=0;j<4;j++){
                int nb = hn*32 + j*8 + g;
                unsigned bh[2], bl[2];
                tfsplit(k_s[nb*PS + kc + tig],     bh[0], bl[0]);
                tfsplit(k_s[nb*PS + kc + tig + 4], bh[1], bl[1]);
                mma_tf32(sc4[j], ah, bh);
                mma_tf32(sc4[j], ah, bl);
                mma_tf32(sc4[j], al, bh);
            }
        }

        // ---- mask + scale + row max ----
        float mx0 = -INFINITY, mx1 = -INFINITY;
        bool okr0 = true, okr1 = true;
        if (MODE==0){ okr0 = (msk_s[r0]>>n)&1u; okr1 = (msk_s[r1]>>n)&1u; }
        #pragma unroll
        for (int j=0;j<4;j++){
            #pragma unroll
            for (int e=0;e<4;e++){
                int row = (e>=2)? r1 : r0;
                int qg  = q0 + row;
                int t   = n*64 + hn*32 + j*8 + 2*tig + (e&1);
                bool ok;
                if (MODE==0) ok = (e>=2)? okr1 : okr0;
                else ok = (t <= qg) && (qg - t <= 512);
                float val = ok ? sc4[j][e]*scale : -INFINITY;
                sc4[j][e] = val;
                if (e<2) mx0 = fmaxf(mx0, val); else mx1 = fmaxf(mx1, val);
            }
        }
        #pragma unroll
        for (int off=1;off<4;off<<=1){
            mx0 = fmaxf(mx0, __shfl_xor_sync(0xffffffffu, mx0, off));
            mx1 = fmaxf(mx1, __shfl_xor_sync(0xffffffffu, mx1, off));
        }
        if (tig==0){ redmx[hn*64 + r0] = mx0; redmx[hn*64 + r1] = mx1; }
        __syncthreads();

        float mo0 = m_s[r0], mo1 = m_s[r1];
        float mn0 = fmaxf(mo0, fmaxf(redmx[r0], redmx[64+r0]));
        float mn1 = fmaxf(mo1, fmaxf(redmx[r1], redmx[64+r1]));
        float al0 = 1.f, al1 = 1.f;
        float sm0 = 0.f, sm1 = 0.f;
        if (mn0 != -INFINITY) al0 = __expf(mo0 - mn0);
        if (mn1 != -INFINITY) al1 = __expf(mo1 - mn1);
        #pragma unroll
        for (int j=0;j<4;j++){
            #pragma unroll
            for (int e=0;e<4;e++){
                float mn = (e>=2)? mn1 : mn0;
                float p = (mn == -INFINITY) ? 0.f : __expf(sc4[j][e] - mn);
                sc4[j][e] = p;
                if (e<2) sm0 += p; else sm1 += p;
            }
        }
        #pragma unroll
        for (int off=1;off<4;off<<=1){
            sm0 += __shfl_xor_sync(0xffffffffu, sm0, off);
            sm1 += __shfl_xor_sync(0xffffffffu, sm1, off);
        }
        if (tig==0){ redsm[hn*64 + r0] = sm0; redsm[hn*64 + r1] = sm1; }
        // write P to smem
        #pragma unroll
        for (int j=0;j<4;j++){
            int cb = hn*32 + j*8 + 2*tig;
            p_s[r0*PS + cb]   = sc4[j][0];
            p_s[r0*PS + cb+1] = sc4[j][1];
            p_s[r1*PS + cb]   = sc4[j][2];
            p_s[r1*PS + cb+1] = sc4[j][3];
        }
        // rescale accumulators
        #pragma unroll
        for (int j=0;j<4;j++){
            acc[j][0]*=al0; acc[j][1]*=al0; acc[j][2]*=al1; acc[j][3]*=al1;
        }
        __syncthreads();
        if (hn==0 && tig==0){
            m_s[r0] = mn0; l_s[r0] = l_s[r0]*al0 + redsm[r0] + redsm[64+r0];
            m_s[r1] = mn1; l_s[r1] = l_s[r1]*al1 + redsm[r1] + redsm[64+r1];
        }

        // ---- O += P V ----
        #pragma unroll
        for (int kc=0;kc<64;kc+=8){
            unsigned ah[4], al2[4];
            tfsplit(p_s[r0*PS + kc + tig],     ah[0], al2[0]);
            tfsplit(p_s[r1*PS + kc + tig],     ah[1], al2[1]);
            tfsplit(p_s[r0*PS + kc + tig + 4], ah[2], al2[2]);
            tfsplit(p_s[r1*PS + kc + tig + 4], ah[3], al2[3]);
            #pragma unroll
            for (int j=0;j<4;j++){
                int nb = hn*32 + j*8 + g;
                unsigned bh[2], bl[2];
                tfsplit(v_s[(kc+tig)*PS + nb],     bh[0], bl[0]);
                tfsplit(v_s[(kc+tig+4)*PS + nb],   bh[1], bl[1]);
                mma_tf32(acc[j], ah, bh);
                mma_tf32(acc[j], ah, bl);
                mma_tf32(acc[j], al2, bh);
            }
        }
        __syncthreads();
    }

    // ---- epilogue ----
    float l0 = l_s[r0], l1 = l_s[r1];
    float in0 = (l0 > 0.f) ? 1.f/l0 : 0.f;
    float in1 = (l1 > 0.f) ? 1.f/l1 : 0.f;
    const int gi = (MODE==0) ? 1 : 2;
    float g0 = d_gate[(q0+r0)*GDIM + h*3 + gi];
    float g1 = d_gate[(q0+r1)*GDIM + h*3 + gi];
    float* outp = (MODE==0) ? d_o2 : d_o3;
    #pragma unroll
    for (int j=0;j<4;j++){
        int cb = hn*32 + j*8 + 2*tig;
        outp[(q0+r0)*DIMM + h*64 + cb]   = g0*acc[j][0]*in0;
        outp[(q0+r0)*DIMM + h*64 + cb+1] = g0*acc[j][1]*in0;
        outp[(q0+r1)*DIMM + h*64 + cb]   = g1*acc[j][2]*in1;
        outp[(q0+r1)*DIMM + h*64 + cb+1] = g1*acc[j][3]*in1;
    }
}

// ---------------- launch ----------------
static cudaStream_t sA = nullptr, sB = nullptr;
static cudaEvent_t e0, e_qkv, e_gate, e_cmp, e_f0, e_f1;

extern "C" void kernel_launch(void* const* d_in, const int* in_sizes, int n_in,
                              void* d_out, int out_size)
{
    (void)in_sizes; (void)n_in; (void)out_size;
    const float* x      = (const float*)d_in[0];
    const float* wq     = (const float*)d_in[1];
    const float* wk     = (const float*)d_in[2];
    const float* wv     = (const float*)d_in[3];
    const float* wo     = (const float*)d_in[4];
    const float* gw1    = (const float*)d_in[5];
    const float* gw2    = (const float*)d_in[6];
    const float* pe_k   = (const float*)d_in[7];
    const float* down_k = (const float*)d_in[8];
    const float* stop_k = (const float*)d_in[9];
    const float* pe_v   = (const float*)d_in[10];
    const float* down_v = (const float*)d_in[11];
    const float* stop_v = (const float*)d_in[12];

    const int GSM = 4*2*BK*ASTR*4;
    const int CSM = (128*65 + 8192 + 64+128+32+64+4)*4;
    const int FSM = (4*64*PS + 64 + 64 + 128 + 128)*4 + (64+1)*4 + 16;

    if (!sA){
        cudaStreamCreateWithFlags(&sA, cudaStreamNonBlocking);
        cudaStreamCreateWithFlags(&sB, cudaStreamNonBlocking);
        cudaEventCreateWithFlags(&e0,     cudaEventDisableTiming);
        cudaEventCreateWithFlags(&e_qkv,  cudaEventDisableTiming);
        cudaEventCreateWithFlags(&e_gate, cudaEventDisableTiming);
        cudaEventCreateWithFlags(&e_cmp,  cudaEventDisableTiming);
        cudaEventCreateWithFlags(&e_f0,   cudaEventDisableTiming);
        cudaEventCreateWithFlags(&e_f1,   cudaEventDisableTiming);
        cudaFuncSetAttribute(gemm_tc,  cudaFuncAttributeMaxDynamicSharedMemorySize, GSM);
        cudaFuncSetAttribute(cmp_attn, cudaFuncAttributeMaxDynamicSharedMemorySize, CSM);
        cudaFuncSetAttribute(attn_flash<0>, cudaFuncAttributeMaxDynamicSharedMemorySize, FSM);
        cudaFuncSetAttribute(attn_flash<1>, cudaFuncAttributeMaxDynamicSharedMemorySize, FSM);
    }

    float *q_p, *k_p, *v_p, *g1_p, *gate_p, *kc_p, *vc_p, *o1_p, *o2_p, *o3_p;
    cudaGetSymbolAddress((void**)&q_p,    d_q);
    cudaGetSymbolAddress((void**)&k_p,    d_k);
    cudaGetSymbolAddress((void**)&v_p,    d_v);
    cudaGetSymbolAddress((void**)&g1_p,   d_g1);
    cudaGetSymbolAddress((void**)&gate_p, d_gate);
    cudaGetSymbolAddress((void**)&kc_p,   d_kc);
    cudaGetSymbolAddress((void**)&vc_p,   d_vc);
    cudaGetSymbolAddress((void**)&o1_p,   d_o1);
    cudaGetSymbolAddress((void**)&o2_p,   d_o2);
    cudaGetSymbolAddress((void**)&o3_p,   d_o3);

    const float scale = 0.125f;

    cudaEventRecord(e0, 0);
    cudaStreamWaitEvent(sA, e0, 0);

    // stream0: fused QKV projection
    gemm_tc<<<dim3(8,16,3),256,GSM>>>(x, nullptr, nullptr, wq, wk, wv,
                                      q_p, k_p, v_p, S, 1024, DIMM, EPI_HEAD);
    cudaEventRecord(e_qkv, 0);

    // sA: gate chain
    gemm_tc<<<dim3(4,16,1),256,GSM,sA>>>(x, nullptr, nullptr, gw1, gw1, gw1,
                                         g1_p, g1_p, g1_p, S, 512, DIMM, EPI_SILU);
    gemm_tc<<<dim3(1,16,1),256,GSM,sA>>>(g1_p, nullptr, nullptr, gw2, gw2, gw2,
                                         gate_p, gate_p, gate_p, S, GDIM, 512, EPI_SIGMOID);
    cudaEventRecord(e_gate, sA);

    // stream0: compression, compressed branch (+ masks)
    compress2<<<dim3(32,16,2),256>>>(k_p, v_p, pe_k, down_k, stop_k,
                                     pe_v, down_v, stop_v, kc_p, vc_p);
    cudaStreamWaitEvent(0, e_gate, 0);
    cmp_attn<<<dim3(S/8,16),128,CSM>>>(scale);
    cudaEventRecord(e_cmp, 0);

    // sA: sliding-window branch
    cudaStreamWaitEvent(sA, e_qkv, 0);
    attn_flash<1><<<dim3(S/64,16),256,FSM,sA>>>(scale);
    cudaEventRecord(e_f1, sA);

    // sB: selection branch
    cudaStreamWaitEvent(sB, e_cmp, 0);
    cudaStreamWaitEvent(sB, e_gate, 0);
    attn_flash<0><<<dim3(S/64,16),256,FSM,sB>>>(scale);
    cudaEventRecord(e_f0, sB);

    // join + output projection
    cudaStreamWaitEvent(0, e_f1, 0);
    cudaStreamWaitEvent(0, e_f0, 0);
    gemm_tc<<<dim3(8,16,1),256,GSM>>>(o1_p, o2_p, o3_p, wo, wo, wo,
                                      (float*)d_out, (float*)d_out, (float*)d_out,
                                      S, DIMM, DIMM, EPI_NONE);
}